// round 1
// baseline (speedup 1.0000x reference)
#include <cuda_runtime.h>
#include <cstdint>

#define GNUM 40     // B*T graphs
#define NN   2000   // nodes per graph
#define E0   16000  // original edges
#define ET   18000  // edges + self loops
#define TT   10
#define BB   4

// ---------------- scratch (device globals; no allocations allowed) ----------------
__device__ float g_xl[GNUM * NN * 128];
__device__ float g_xr[GNUM * NN * 128];
__device__ float g_hA[GNUM * NN * 128];
__device__ float g_hB[GNUM * NN * 128];
__device__ float g_ee[ET * 128];
__device__ float g_logits[GNUM * ET * 4];
__device__ int   g_src[ET];
__device__ int   g_dst[ET];
__device__ int   g_deg[NN];
__device__ int   g_rowstart[NN + 1];
__device__ int   g_cursor[NN];
__device__ int   g_perm[ET];
__device__ float g_eamean[2];
__device__ float g_gates[GNUM * 1024];
__device__ float g_hstate[BB * 256];
__device__ float g_cstate[BB * 256];

// ---------------- edge_attr mean (for self-loop fill) ----------------
__global__ void k_ea_mean(const float* __restrict__ ea) {
    __shared__ float s0[256], s1[256];
    int t = threadIdx.x;
    float a = 0.f, b = 0.f;
    for (int e = t; e < E0; e += 256) { a += ea[2 * e]; b += ea[2 * e + 1]; }
    s0[t] = a; s1[t] = b;
    __syncthreads();
    for (int o = 128; o; o >>= 1) {
        if (t < o) { s0[t] += s0[t + o]; s1[t] += s1[t + o]; }
        __syncthreads();
    }
    if (t == 0) { g_eamean[0] = s0[0] / E0; g_eamean[1] = s1[0] / E0; }
}

// ---------------- edge list with self loops + in-degree histogram ----------------
__global__ void k_edges_prep(const int* __restrict__ ei) {
    int e = blockIdx.x * blockDim.x + threadIdx.x;
    if (e >= ET) return;
    int s, d;
    if (e < E0) { s = ei[e]; d = ei[E0 + e]; }
    else        { s = d = e - E0; }
    g_src[e] = s; g_dst[e] = d;
    atomicAdd(&g_deg[d], 1);
}

// exclusive scan over 2000 degrees (single block, chunked)
__global__ void k_scan() {
    __shared__ int csum[256];
    __shared__ int cpre[257];
    int t = threadIdx.x;
    int c0 = t * 8;
    int local[8];
    int s = 0;
    for (int i = 0; i < 8; i++) {
        int idx = c0 + i;
        int dv = (idx < NN) ? g_deg[idx] : 0;
        local[i] = s; s += dv;
    }
    csum[t] = s;
    __syncthreads();
    if (t == 0) {
        int acc = 0;
        for (int i = 0; i < 256; i++) { cpre[i] = acc; acc += csum[i]; }
        cpre[256] = acc;
    }
    __syncthreads();
    for (int i = 0; i < 8; i++) {
        int idx = c0 + i;
        if (idx < NN) {
            int v = cpre[t] + local[i];
            g_rowstart[idx] = v;
            g_cursor[idx]   = v;
        }
    }
    if (t == 0) g_rowstart[NN] = cpre[256];
}

__global__ void k_scatter() {
    int e = blockIdx.x * blockDim.x + threadIdx.x;
    if (e >= ET) return;
    int d = g_dst[e];
    int pos = atomicAdd(&g_cursor[d], 1);
    g_perm[pos] = e;
}

// ---------------- edge-feature projection ee = ea @ We  [ET, HC] ----------------
__global__ void k_ee(const float* __restrict__ ea, const float* __restrict__ We, int HC) {
    int i = blockIdx.x * blockDim.x + threadIdx.x;
    if (i >= ET * HC) return;
    int e = i / HC, j = i - e * HC;
    float a0, a1;
    if (e < E0) { a0 = ea[2 * e]; a1 = ea[2 * e + 1]; }
    else        { a0 = g_eamean[0]; a1 = g_eamean[1]; }
    g_ee[i] = a0 * We[j] + a1 * We[HC + j];
}

// ---------------- generic tiled GEMM: two B matrices in one launch (z=0 -> C0, z=1 -> C1)
// C[M,N] = A[M,K] @ B[K,N], all row-major, fp32
__global__ void k_gemm2(const float* __restrict__ A,
                        const float* __restrict__ B0, const float* __restrict__ B1,
                        float* __restrict__ C0, float* __restrict__ C1,
                        int M, int N, int K) {
    const float* B = blockIdx.z ? B1 : B0;
    float*       C = blockIdx.z ? C1 : C0;
    __shared__ float As[8][64];
    __shared__ float Bs[8][64];
    int tid = threadIdx.x;
    int tx = tid & 15, ty = tid >> 4;
    int m0 = blockIdx.y * 64, n0 = blockIdx.x * 64;
    float acc[4][4] = {};
    for (int k0 = 0; k0 < K; k0 += 8) {
#pragma unroll
        for (int it = 0; it < 2; it++) {
            int idx = tid + it * 256;
            int r = idx >> 3, kk = idx & 7;
            float v = 0.f;
            if (m0 + r < M && k0 + kk < K) v = A[(size_t)(m0 + r) * K + k0 + kk];
            As[kk][r] = v;
            int kk2 = idx >> 6, c = idx & 63;
            float v2 = 0.f;
            if (k0 + kk2 < K && n0 + c < N) v2 = B[(size_t)(k0 + kk2) * N + n0 + c];
            Bs[kk2][c] = v2;
        }
        __syncthreads();
#pragma unroll
        for (int kk = 0; kk < 8; kk++) {
            float4 a4 = ((const float4*)As[kk])[ty];
            float4 b4 = ((const float4*)Bs[kk])[tx];
            float av[4] = {a4.x, a4.y, a4.z, a4.w};
            float bv[4] = {b4.x, b4.y, b4.z, b4.w};
#pragma unroll
            for (int i = 0; i < 4; i++)
#pragma unroll
                for (int jj = 0; jj < 4; jj++) acc[i][jj] += av[i] * bv[jj];
        }
        __syncthreads();
    }
#pragma unroll
    for (int i = 0; i < 4; i++) {
        int m = m0 + ty * 4 + i;
        if (m >= M) continue;
#pragma unroll
        for (int jj = 0; jj < 4; jj++) {
            int n = n0 + tx * 4 + jj;
            if (n < N) C[(size_t)m * N + n] = acc[i][jj];
        }
    }
}

// ---------------- per-edge attention logits (one warp per (graph, edge)) ----------------
template <int C>
__global__ void k_logits(const float* __restrict__ att) {
    int gid  = blockIdx.x * (blockDim.x >> 5) + (threadIdx.x >> 5);
    int lane = threadIdx.x & 31;
    if (gid >= GNUM * ET) return;
    int g = gid / ET, e = gid - g * ET;
    int s = g_src[e], d = g_dst[e];
    const int HC = 4 * C;
    const float* xl = g_xl + ((size_t)g * NN + s) * HC;
    const float* xr = g_xr + ((size_t)g * NN + d) * HC;
    const float* ee = g_ee + (size_t)e * HC;
    float* lo = g_logits + ((size_t)g * ET + e) * 4;
    if (C == 32) {
#pragma unroll
        for (int h = 0; h < 4; h++) {
            int j = h * 32 + lane;
            float v = xl[j] + xr[j] + ee[j];
            v = v > 0.f ? v : 0.2f * v;
            v *= att[j];
#pragma unroll
            for (int o = 16; o; o >>= 1) v += __shfl_xor_sync(0xffffffffu, v, o);
            if (lane == 0) lo[h] = v;
        }
    } else {  // C == 8, all 4 heads in one pass
        int j = lane;
        float v = xl[j] + xr[j] + ee[j];
        v = v > 0.f ? v : 0.2f * v;
        v *= att[j];
        v += __shfl_xor_sync(0xffffffffu, v, 4);
        v += __shfl_xor_sync(0xffffffffu, v, 2);
        v += __shfl_xor_sync(0xffffffffu, v, 1);
        if ((lane & 7) == 0) lo[lane >> 3] = v;
    }
}

// ---------------- per-node softmax + aggregation (one warp per (graph, node)) -----------
// two-loop trick: loop1 max, loop2 accumulate p and p*xl; divide by denom at the end.
template <int C>
__global__ void k_aggr(const float* __restrict__ bias, float* __restrict__ out) {
    int gid  = blockIdx.x * (blockDim.x >> 5) + (threadIdx.x >> 5);
    int lane = threadIdx.x & 31;
    if (gid >= GNUM * NN) return;
    int g = gid / NN, d = gid - g * NN;
    const int HC = 4 * C;
    const int HP = 32 / C;           // heads per pass
    int rs = g_rowstart[d], re = g_rowstart[d + 1];
    const float* lo_base = g_logits + (size_t)g * ET * 4;
    const float* xlg     = g_xl + (size_t)g * NN * HC;
#pragma unroll
    for (int p = 0; p < 4 / HP; p++) {
        int h = p * HP + lane / C;
        int c = lane % C;
        float mx = -1e30f;
        for (int i = rs; i < re; i++) {
            int e = g_perm[i];
            mx = fmaxf(mx, lo_base[e * 4 + h]);
        }
        float den = 0.f, acc = 0.f;
        for (int i = rs; i < re; i++) {
            int e = g_perm[i];
            float pv = __expf(lo_base[e * 4 + h] - mx);
            den += pv;
            int s = g_src[e];
            acc += pv * xlg[(size_t)s * HC + h * C + c];
        }
        float o = acc / (den + 1e-16f) + bias[h * C + c];
        out[((size_t)g * NN + d) * HC + h * C + c] = fmaxf(o, 0.f);  // relu fused
    }
}

// ---------------- LSTM input projection: gates = emb @ w_ih^T + b_ih + b_hh -------------
__global__ void k_init_gates(const float* __restrict__ bih, const float* __restrict__ bhh) {
    int i = blockIdx.x * blockDim.x + threadIdx.x;
    if (i >= GNUM * 1024) return;
    int j = i & 1023;
    g_gates[i] = bih[j] + bhh[j];
}

// grid (125 k-chunks of 512, 16 j-tiles of 64); emb chunk [40][512] in smem (80 KB)
__global__ void k_gates_gemm(const float* __restrict__ emb, const float* __restrict__ wih) {
    extern __shared__ float es[];  // GNUM*512 floats
    int k0 = blockIdx.x * 512;
    int jt = blockIdx.y;
    int tid = threadIdx.x;
    for (int idx = tid; idx < GNUM * 512; idx += 256) {
        int r = idx >> 9, k = idx & 511;
        es[idx] = emb[(size_t)r * 64000 + k0 + k];
    }
    __syncthreads();
    int w = tid >> 5, lane = tid & 31;
    for (int grp = 0; grp < 2; grp++) {
        int jb = jt * 64 + w * 8 + grp * 4;
        float wv[4][16];
#pragma unroll
        for (int jj = 0; jj < 4; jj++) {
            const float* wp = wih + (size_t)(jb + jj) * 64000 + k0 + lane;
#pragma unroll
            for (int kk = 0; kk < 16; kk++) wv[jj][kk] = wp[kk * 32];
        }
        for (int b = 0; b < GNUM; b++) {
            float a0 = 0, a1 = 0, a2 = 0, a3 = 0;
            const float* eb = es + b * 512 + lane;
#pragma unroll
            for (int kk = 0; kk < 16; kk++) {
                float ev = eb[kk * 32];
                a0 += ev * wv[0][kk]; a1 += ev * wv[1][kk];
                a2 += ev * wv[2][kk]; a3 += ev * wv[3][kk];
            }
#pragma unroll
            for (int o = 16; o; o >>= 1) {
                a0 += __shfl_xor_sync(0xffffffffu, a0, o);
                a1 += __shfl_xor_sync(0xffffffffu, a1, o);
                a2 += __shfl_xor_sync(0xffffffffu, a2, o);
                a3 += __shfl_xor_sync(0xffffffffu, a3, o);
            }
            if (lane == 0) {
                atomicAdd(&g_gates[b * 1024 + jb + 0], a0);
                atomicAdd(&g_gates[b * 1024 + jb + 1], a1);
                atomicAdd(&g_gates[b * 1024 + jb + 2], a2);
                atomicAdd(&g_gates[b * 1024 + jb + 3], a3);
            }
        }
    }
}

// ---------------- one LSTM timestep (single block, 1024 threads) ----------------
__device__ __forceinline__ float sigf(float x) { return 1.f / (1.f + __expf(-x)); }

__global__ void k_lstm_step(const float* __restrict__ whh, int t) {
    __shared__ float hs[BB * 256];
    __shared__ float gsm[BB * 1024];
    int j = threadIdx.x;
    hs[j] = g_hstate[j];
    __syncthreads();
    float acc[BB];
#pragma unroll
    for (int b = 0; b < BB; b++) acc[b] = g_gates[(size_t)(b * TT + t) * 1024 + j];
    const float* wr = whh + (size_t)j * 256;
    for (int k = 0; k < 256; k += 4) {
        float4 w4 = *(const float4*)(wr + k);
#pragma unroll
        for (int b = 0; b < BB; b++) {
            acc[b] += hs[b * 256 + k]     * w4.x + hs[b * 256 + k + 1] * w4.y
                    + hs[b * 256 + k + 2] * w4.z + hs[b * 256 + k + 3] * w4.w;
        }
    }
#pragma unroll
    for (int b = 0; b < BB; b++) gsm[b * 1024 + j] = acc[b];
    __syncthreads();
    if (j < 256) {
#pragma unroll
        for (int b = 0; b < BB; b++) {
            float iv = gsm[b * 1024 + j];
            float fv = gsm[b * 1024 + 256 + j];
            float gv = gsm[b * 1024 + 512 + j];
            float ov = gsm[b * 1024 + 768 + j];
            float c = sigf(fv) * g_cstate[b * 256 + j] + sigf(iv) * tanhf(gv);
            g_cstate[b * 256 + j] = c;
            g_hstate[b * 256 + j] = sigf(ov) * tanhf(c);
        }
    }
}

// ---------------- final FCs: relu(h) -> fc1 -> relu -> fc2 ----------------
__global__ void k_fc(const float* __restrict__ fc1w, const float* __restrict__ fc1b,
                     const float* __restrict__ fc2w, const float* __restrict__ fc2b,
                     float* __restrict__ out) {
    __shared__ float last[BB * 256];
    __shared__ float hid[BB * 512];
    __shared__ float red[512];
    int j = threadIdx.x;  // 512 threads
    last[j]       = fmaxf(g_hstate[j], 0.f);
    last[j + 512] = fmaxf(g_hstate[j + 512], 0.f);
    __syncthreads();
    for (int b = 0; b < BB; b++) {
        float acc = fc1b[j];
        for (int k = 0; k < 256; k++) acc += last[b * 256 + k] * fc1w[k * 512 + j];
        hid[b * 512 + j] = fmaxf(acc, 0.f);
    }
    __syncthreads();
    for (int b = 0; b < BB; b++) {
        red[j] = hid[b * 512 + j] * fc2w[j];
        __syncthreads();
        for (int o = 256; o; o >>= 1) {
            if (j < o) red[j] += red[j + o];
            __syncthreads();
        }
        if (j == 0) out[b] = red[0] + fc2b[0];
        __syncthreads();
    }
}

// ---------------- host launcher ----------------
extern "C" void kernel_launch(void* const* d_in, const int* in_sizes, int n_in,
                              void* d_out, int out_size) {
    const float* x    = (const float*)d_in[0];
    const int*   ei   = (const int*)d_in[1];
    const float* ea   = (const float*)d_in[2];
    const float* wl0  = (const float*)d_in[3];
    const float* wr0  = (const float*)d_in[4];
    const float* we0  = (const float*)d_in[5];
    const float* att0 = (const float*)d_in[6];
    const float* b0   = (const float*)d_in[7];
    const float* wl1  = (const float*)d_in[8];
    const float* wr1  = (const float*)d_in[9];
    const float* we1  = (const float*)d_in[10];
    const float* att1 = (const float*)d_in[11];
    const float* b1   = (const float*)d_in[12];
    const float* wl2  = (const float*)d_in[13];
    const float* wr2  = (const float*)d_in[14];
    const float* we2  = (const float*)d_in[15];
    const float* att2 = (const float*)d_in[16];
    const float* b2   = (const float*)d_in[17];
    const float* wih  = (const float*)d_in[18];
    const float* whh  = (const float*)d_in[19];
    const float* bih  = (const float*)d_in[20];
    const float* bhh  = (const float*)d_in[21];
    const float* fc1w = (const float*)d_in[22];
    const float* fc1b = (const float*)d_in[23];
    const float* fc2w = (const float*)d_in[24];
    const float* fc2b = (const float*)d_in[25];

    void *p_xl, *p_xr, *p_hA, *p_hB, *p_deg, *p_h, *p_c;
    cudaGetSymbolAddress(&p_xl, g_xl);
    cudaGetSymbolAddress(&p_xr, g_xr);
    cudaGetSymbolAddress(&p_hA, g_hA);
    cudaGetSymbolAddress(&p_hB, g_hB);
    cudaGetSymbolAddress(&p_deg, g_deg);
    cudaGetSymbolAddress(&p_h, g_hstate);
    cudaGetSymbolAddress(&p_c, g_cstate);
    float* xl = (float*)p_xl;
    float* xr = (float*)p_xr;
    float* hA = (float*)p_hA;
    float* hB = (float*)p_hB;

    cudaMemsetAsync(p_deg, 0, NN * sizeof(int));
    cudaMemsetAsync(p_h, 0, BB * 256 * sizeof(float));
    cudaMemsetAsync(p_c, 0, BB * 256 * sizeof(float));

    k_ea_mean<<<1, 256>>>(ea);
    k_edges_prep<<<(ET + 255) / 256, 256>>>(ei);
    k_scan<<<1, 256>>>();
    k_scatter<<<(ET + 255) / 256, 256>>>();

    const int M = GNUM * NN;  // 80000
    int logit_blocks = (GNUM * ET + 7) / 8;  // 8 warps/block
    int aggr_blocks  = (GNUM * NN + 7) / 8;

    // ---- layer 0: 8 -> 128 (H=4, C=32) ----
    k_ee<<<(ET * 128 + 255) / 256, 256>>>(ea, we0, 128);
    k_gemm2<<<dim3(2, (M + 63) / 64, 2), 256>>>(x, wl0, wr0, xl, xr, M, 128, 8);
    k_logits<32><<<logit_blocks, 256>>>(att0);
    k_aggr<32><<<aggr_blocks, 256>>>(b0, hA);

    // ---- layer 1: 128 -> 128 ----
    k_ee<<<(ET * 128 + 255) / 256, 256>>>(ea, we1, 128);
    k_gemm2<<<dim3(2, (M + 63) / 64, 2), 256>>>(hA, wl1, wr1, xl, xr, M, 128, 128);
    k_logits<32><<<logit_blocks, 256>>>(att1);
    k_aggr<32><<<aggr_blocks, 256>>>(b1, hB);

    // ---- layer 2: 128 -> 32 (H=4, C=8) ----
    k_ee<<<(ET * 32 + 255) / 256, 256>>>(ea, we2, 32);
    k_gemm2<<<dim3(1, (M + 63) / 64, 2), 256>>>(hB, wl2, wr2, xl, xr, M, 32, 128);
    k_logits<8><<<logit_blocks, 256>>>(att2);
    k_aggr<8><<<aggr_blocks, 256>>>(b2, hA);  // hA now holds emb [40][64000]

    // ---- LSTM input projection ----
    k_init_gates<<<(GNUM * 1024 + 255) / 256, 256>>>(bih, bhh);
    cudaFuncSetAttribute(k_gates_gemm, cudaFuncAttributeMaxDynamicSharedMemorySize,
                         GNUM * 512 * sizeof(float));
    k_gates_gemm<<<dim3(125, 16), 256, GNUM * 512 * sizeof(float)>>>(hA, wih);

    // ---- LSTM scan + head ----
    for (int t = 0; t < TT; t++) k_lstm_step<<<1, 1024>>>(whh, t);
    k_fc<<<1, 512>>>(fc1w, fc1b, fc2w, fc2b, (float*)d_out);
}

// round 2
// speedup vs baseline: 1.3430x; 1.3430x over previous
#include <cuda_runtime.h>
#include <cstdint>

#define GNUM 40     // B*T graphs
#define NN   2000   // nodes per graph
#define E0   16000  // original edges
#define ET   18000  // edges + self loops
#define TT   10
#define BB   4

// ---------------- scratch (device globals; no allocations allowed) ----------------
__device__ float g_xl[GNUM * NN * 128];
__device__ float g_xr[GNUM * NN * 128];
__device__ float g_hA[GNUM * NN * 128];
__device__ float g_hB[GNUM * NN * 128];
__device__ float g_ee[ET * 128];          // permuted (CSR order) edge projections
__device__ int   g_src[ET];
__device__ int   g_dst[ET];
__device__ int   g_deg[NN];
__device__ int   g_rowstart[NN + 1];
__device__ int   g_cursor[NN];
__device__ int   g_perm[ET];              // CSR pos -> original edge id
__device__ int   g_psrc[ET];              // CSR pos -> src node
__device__ float g_eamean[2];
__device__ float g_gates[GNUM * 1024];
__device__ float g_gacc[BB * 1024];
__device__ float g_whht[256 * 1024];
__device__ float g_hstate[BB * 256];
__device__ float g_cstate[BB * 256];

// ---------------- edge_attr mean (for self-loop fill) ----------------
__global__ void k_ea_mean(const float* __restrict__ ea) {
    __shared__ float s0[256], s1[256];
    int t = threadIdx.x;
    float a = 0.f, b = 0.f;
    for (int e = t; e < E0; e += 256) { a += ea[2 * e]; b += ea[2 * e + 1]; }
    s0[t] = a; s1[t] = b;
    __syncthreads();
    for (int o = 128; o; o >>= 1) {
        if (t < o) { s0[t] += s0[t + o]; s1[t] += s1[t + o]; }
        __syncthreads();
    }
    if (t == 0) { g_eamean[0] = s0[0] / E0; g_eamean[1] = s1[0] / E0; }
}

// ---------------- edge list with self loops + in-degree histogram ----------------
__global__ void k_edges_prep(const int* __restrict__ ei) {
    int e = blockIdx.x * blockDim.x + threadIdx.x;
    if (e >= ET) return;
    int s, d;
    if (e < E0) { s = ei[e]; d = ei[E0 + e]; }
    else        { s = d = e - E0; }
    g_src[e] = s; g_dst[e] = d;
    atomicAdd(&g_deg[d], 1);
}

// exclusive scan over 2000 degrees (single block)
__global__ void k_scan() {
    __shared__ int csum[256];
    __shared__ int cpre[257];
    int t = threadIdx.x;
    int c0 = t * 8;
    int local[8];
    int s = 0;
    for (int i = 0; i < 8; i++) {
        int idx = c0 + i;
        int dv = (idx < NN) ? g_deg[idx] : 0;
        local[i] = s; s += dv;
    }
    csum[t] = s;
    __syncthreads();
    if (t == 0) {
        int acc = 0;
        for (int i = 0; i < 256; i++) { cpre[i] = acc; acc += csum[i]; }
        cpre[256] = acc;
    }
    __syncthreads();
    for (int i = 0; i < 8; i++) {
        int idx = c0 + i;
        if (idx < NN) {
            int v = cpre[t] + local[i];
            g_rowstart[idx] = v;
            g_cursor[idx]   = v;
        }
    }
    if (t == 0) g_rowstart[NN] = cpre[256];
}

__global__ void k_scatter() {
    int e = blockIdx.x * blockDim.x + threadIdx.x;
    if (e >= ET) return;
    int d = g_dst[e];
    int pos = atomicAdd(&g_cursor[d], 1);
    g_perm[pos] = e;
    g_psrc[pos] = g_src[e];
}

// ---------------- permuted edge-feature projection ee_p[pos] = ea[perm[pos]] @ We ------
__global__ void k_eep(const float* __restrict__ ea, const float* __restrict__ We, int HC) {
    int i = blockIdx.x * blockDim.x + threadIdx.x;
    if (i >= ET * HC) return;
    int pos = i / HC, j = i - pos * HC;
    int e = g_perm[pos];
    float a0, a1;
    if (e < E0) { a0 = ea[2 * e]; a1 = ea[2 * e + 1]; }
    else        { a0 = g_eamean[0]; a1 = g_eamean[1]; }
    g_ee[i] = a0 * We[j] + a1 * We[HC + j];
}

// ---------------- GEMM N=128: C[M,128] = A[M,K] @ B[K,128]; M%128==0, K%8==0 ------------
// 128x128x8 tile, 256 threads, 8x8 microtile. z selects (B0->C0)/(B1->C1).
__global__ void k_gemm_n128(const float* __restrict__ A,
                            const float* __restrict__ B0, const float* __restrict__ B1,
                            float* __restrict__ C0, float* __restrict__ C1, int K) {
    const float* B = blockIdx.z ? B1 : B0;
    float*       C = blockIdx.z ? C1 : C0;
    __shared__ float As[8][128];
    __shared__ float Bs[8][128];
    int tid = threadIdx.x;
    int m0 = blockIdx.y * 128;
    int arow = tid >> 1, acol4 = (tid & 1) * 4;
    int brow = tid >> 5, bcol = (tid & 31) * 4;
    int tx = tid & 15, ty = tid >> 4;
    float acc[8][8] = {};
    for (int k0 = 0; k0 < K; k0 += 8) {
        float4 av = *(const float4*)(A + (size_t)(m0 + arow) * K + k0 + acol4);
        As[acol4 + 0][arow] = av.x; As[acol4 + 1][arow] = av.y;
        As[acol4 + 2][arow] = av.z; As[acol4 + 3][arow] = av.w;
        *(float4*)&Bs[brow][bcol] = *(const float4*)(B + (size_t)(k0 + brow) * 128 + bcol);
        __syncthreads();
#pragma unroll
        for (int kk = 0; kk < 8; kk++) {
            float a[8], b[8];
            *(float4*)a       = *(const float4*)&As[kk][ty * 8];
            *(float4*)(a + 4) = *(const float4*)&As[kk][ty * 8 + 4];
            *(float4*)b       = *(const float4*)&Bs[kk][tx * 8];
            *(float4*)(b + 4) = *(const float4*)&Bs[kk][tx * 8 + 4];
#pragma unroll
            for (int i = 0; i < 8; i++)
#pragma unroll
                for (int j = 0; j < 8; j++) acc[i][j] += a[i] * b[j];
        }
        __syncthreads();
    }
#pragma unroll
    for (int i = 0; i < 8; i++) {
        float* cp = C + (size_t)(m0 + ty * 8 + i) * 128 + tx * 8;
        *(float4*)cp       = *(float4*)&acc[i][0];
        *(float4*)(cp + 4) = *(float4*)&acc[i][4];
    }
}

// ---------------- GEMM N=32: C[M,32] = A[M,128] @ B[128,32]; 128x32x16 tile -------------
__global__ void k_gemm_n32(const float* __restrict__ A,
                           const float* __restrict__ B0, const float* __restrict__ B1,
                           float* __restrict__ C0, float* __restrict__ C1) {
    const float* B = blockIdx.z ? B1 : B0;
    float*       C = blockIdx.z ? C1 : C0;
    __shared__ float As[16][128];
    __shared__ float Bs[16][32];
    int tid = threadIdx.x;
    int m0 = blockIdx.y * 128;
    int tx = tid & 15, ty = tid >> 4;
    float acc[8][2] = {};
    for (int k0 = 0; k0 < 128; k0 += 16) {
#pragma unroll
        for (int it = 0; it < 2; it++) {
            int idx = tid + it * 256;
            int ar = idx >> 2, ac4 = (idx & 3) * 4;
            float4 av = *(const float4*)(A + (size_t)(m0 + ar) * 128 + k0 + ac4);
            As[ac4 + 0][ar] = av.x; As[ac4 + 1][ar] = av.y;
            As[ac4 + 2][ar] = av.z; As[ac4 + 3][ar] = av.w;
        }
        if (tid < 128) {
            int br = tid >> 3, bc = (tid & 7) * 4;
            *(float4*)&Bs[br][bc] = *(const float4*)(B + (size_t)(k0 + br) * 32 + bc);
        }
        __syncthreads();
#pragma unroll
        for (int kk = 0; kk < 16; kk++) {
            float a[8];
            *(float4*)a       = *(const float4*)&As[kk][ty * 8];
            *(float4*)(a + 4) = *(const float4*)&As[kk][ty * 8 + 4];
            float b0v = Bs[kk][tx * 2], b1v = Bs[kk][tx * 2 + 1];
#pragma unroll
            for (int i = 0; i < 8; i++) { acc[i][0] += a[i] * b0v; acc[i][1] += a[i] * b1v; }
        }
        __syncthreads();
    }
#pragma unroll
    for (int i = 0; i < 8; i++) {
        float2 v; v.x = acc[i][0]; v.y = acc[i][1];
        *(float2*)(C + (size_t)(m0 + ty * 8 + i) * 32 + tx * 2) = v;
    }
}

// ---------------- fused logits + softmax + aggregation (warp per (graph,node)) ----------
// logits are tiny (|l| << 10) so exp(l) is safe without max-subtraction; single edge walk.
template <int C>
__global__ void k_aggr_fused(const float* __restrict__ att, const float* __restrict__ bias,
                             float* __restrict__ out) {
    int gid  = blockIdx.x * (blockDim.x >> 5) + (threadIdx.x >> 5);
    int lane = threadIdx.x & 31;
    if (gid >= GNUM * NN) return;
    int g = gid / NN, d = gid - g * NN;
    int rs = g_rowstart[d], re = g_rowstart[d + 1];
    if (C == 32) {
        const float* xlg = g_xl + (size_t)g * NN * 128;
        const float* xrr = g_xr + ((size_t)g * NN + d) * 128;
        float xrv[4], attv[4], acc[4] = {}, den[4] = {};
#pragma unroll
        for (int h = 0; h < 4; h++) { xrv[h] = xrr[h * 32 + lane]; attv[h] = att[h * 32 + lane]; }
#pragma unroll 2
        for (int i = rs; i < re; i++) {
            int s = g_psrc[i];
            const float* xls = xlg + (size_t)s * 128;
            const float* eer = g_ee + (size_t)i * 128;
            float xlv[4], vv[4];
#pragma unroll
            for (int h = 0; h < 4; h++) xlv[h] = xls[h * 32 + lane];
#pragma unroll
            for (int h = 0; h < 4; h++) {
                float v = xlv[h] + xrv[h] + eer[h * 32 + lane];
                v = v > 0.f ? v : 0.2f * v;
                vv[h] = v * attv[h];
            }
#pragma unroll
            for (int o = 16; o; o >>= 1) {
#pragma unroll
                for (int h = 0; h < 4; h++) vv[h] += __shfl_xor_sync(0xffffffffu, vv[h], o);
            }
#pragma unroll
            for (int h = 0; h < 4; h++) {
                float p = __expf(vv[h]);
                den[h] += p; acc[h] += p * xlv[h];
            }
        }
        float* op = out + ((size_t)g * NN + d) * 128;
#pragma unroll
        for (int h = 0; h < 4; h++)
            op[h * 32 + lane] = fmaxf(acc[h] / (den[h] + 1e-16f) + bias[h * 32 + lane], 0.f);
    } else {  // C == 8, HC = 32
        const float* xlg = g_xl + (size_t)g * NN * 32;
        float xrv = g_xr[((size_t)g * NN + d) * 32 + lane];
        float attv = att[lane];
        float acc = 0.f, den = 0.f;
#pragma unroll 2
        for (int i = rs; i < re; i++) {
            int s = g_psrc[i];
            float xlv = xlg[(size_t)s * 32 + lane];
            float v = xlv + xrv + g_ee[(size_t)i * 32 + lane];
            v = v > 0.f ? v : 0.2f * v;
            v *= attv;
            v += __shfl_xor_sync(0xffffffffu, v, 4);
            v += __shfl_xor_sync(0xffffffffu, v, 2);
            v += __shfl_xor_sync(0xffffffffu, v, 1);
            float p = __expf(v);
            den += p; acc += p * xlv;
        }
        out[((size_t)g * NN + d) * 32 + lane] =
            fmaxf(acc / (den + 1e-16f) + bias[lane], 0.f);
    }
}

// ---------------- LSTM input projection ----------------
__global__ void k_init_gates(const float* __restrict__ bih, const float* __restrict__ bhh) {
    int i = blockIdx.x * blockDim.x + threadIdx.x;
    if (i >= GNUM * 1024) return;
    int j = i & 1023;
    g_gates[i] = bih[j] + bhh[j];
}

// register split-K GEMM: gates[g][j] += sum_k emb[g][k] * wih[j][k]
// grid (125 k-chunks of 512, 16 j-groups of 64). 128 threads = 4 warps; warp covers 4 j,
// 4 passes reuse the smem emb tile (64 j per block). lane = k%32, acc[4][40] in registers.
#define KC 512
__global__ void __launch_bounds__(128)
k_gates2(const float* __restrict__ emb, const float* __restrict__ wih) {
    extern __shared__ float es[];  // [GNUM][KC] = 80 KB
    int k0 = blockIdx.x * KC;
    int tid = threadIdx.x, warp = tid >> 5, lane = tid & 31;
    const float4* e4g = (const float4*)emb;
    float4* es4 = (float4*)es;
    for (int idx = tid; idx < GNUM * KC / 4; idx += 128) {
        int b = idx / (KC / 4), kq = idx - b * (KC / 4);
        es4[idx] = e4g[(size_t)b * 16000 + (k0 >> 2) + kq];
    }
    __syncthreads();
#pragma unroll 1
    for (int pass = 0; pass < 4; pass++) {
        int j0 = blockIdx.y * 64 + pass * 16 + warp * 4;
        float acc[4][GNUM];
#pragma unroll
        for (int jj = 0; jj < 4; jj++)
#pragma unroll
            for (int b = 0; b < GNUM; b++) acc[jj][b] = 0.f;
#pragma unroll 2
        for (int s = 0; s < KC / 128; s++) {
            float4 w4[4];
#pragma unroll
            for (int jj = 0; jj < 4; jj++)
                w4[jj] = *(const float4*)(wih + (size_t)(j0 + jj) * 64000 + k0 + s * 128 + lane * 4);
#pragma unroll
            for (int b = 0; b < GNUM; b++) {
                float4 ev = *(const float4*)(es + b * KC + s * 128 + lane * 4);
#pragma unroll
                for (int jj = 0; jj < 4; jj++) {
                    acc[jj][b] += w4[jj].x * ev.x;
                    acc[jj][b] += w4[jj].y * ev.y;
                    acc[jj][b] += w4[jj].z * ev.z;
                    acc[jj][b] += w4[jj].w * ev.w;
                }
            }
        }
#pragma unroll
        for (int jj = 0; jj < 4; jj++)
#pragma unroll
            for (int b = 0; b < GNUM; b++) {
                float v = acc[jj][b];
                v += __shfl_xor_sync(0xffffffffu, v, 16);
                v += __shfl_xor_sync(0xffffffffu, v, 8);
                v += __shfl_xor_sync(0xffffffffu, v, 4);
                v += __shfl_xor_sync(0xffffffffu, v, 2);
                v += __shfl_xor_sync(0xffffffffu, v, 1);
                if (lane == 0) atomicAdd(&g_gates[b * 1024 + j0 + jj], v);
            }
    }
}

// ---------------- LSTM ----------------
__global__ void k_whht(const float* __restrict__ whh) {  // [1024,256] -> [256,1024]
    int i = blockIdx.x * 256 + threadIdx.x;
    int j = i >> 8, k = i & 255;
    g_whht[k * 1024 + j] = whh[i];
}

__device__ __forceinline__ float sigf(float x) { return 1.f / (1.f + __expf(-x)); }

__global__ void k_lstm_gemm(int t) {  // grid 8 x 128 threads
    __shared__ float hs[BB * 256];
    int tid = threadIdx.x;
    int j = blockIdx.x * 128 + tid;
    for (int i = tid; i < BB * 256; i += 128) hs[i] = g_hstate[i];
    __syncthreads();
    float acc[BB];
#pragma unroll
    for (int b = 0; b < BB; b++) acc[b] = g_gates[(size_t)(b * TT + t) * 1024 + j];
#pragma unroll 4
    for (int k = 0; k < 256; k++) {
        float w = g_whht[k * 1024 + j];
#pragma unroll
        for (int b = 0; b < BB; b++) acc[b] += w * hs[b * 256 + k];
    }
#pragma unroll
    for (int b = 0; b < BB; b++) g_gacc[b * 1024 + j] = acc[b];
}

__global__ void k_lstm_update() {  // 1 block x 256 threads
    int j = threadIdx.x;
#pragma unroll
    for (int b = 0; b < BB; b++) {
        float iv = g_gacc[b * 1024 + j];
        float fv = g_gacc[b * 1024 + 256 + j];
        float gv = g_gacc[b * 1024 + 512 + j];
        float ov = g_gacc[b * 1024 + 768 + j];
        float c = sigf(fv) * g_cstate[b * 256 + j] + sigf(iv) * tanhf(gv);
        g_cstate[b * 256 + j] = c;
        g_hstate[b * 256 + j] = sigf(ov) * tanhf(c);
    }
}

// ---------------- final FCs ----------------
__global__ void k_fc(const float* __restrict__ fc1w, const float* __restrict__ fc1b,
                     const float* __restrict__ fc2w, const float* __restrict__ fc2b,
                     float* __restrict__ out) {
    __shared__ float last[BB * 256];
    __shared__ float hid[BB * 512];
    __shared__ float red[512];
    int j = threadIdx.x;  // 512 threads
    last[j]       = fmaxf(g_hstate[j], 0.f);
    last[j + 512] = fmaxf(g_hstate[j + 512], 0.f);
    __syncthreads();
    for (int b = 0; b < BB; b++) {
        float acc = fc1b[j];
        for (int k = 0; k < 256; k++) acc += last[b * 256 + k] * fc1w[k * 512 + j];
        hid[b * 512 + j] = fmaxf(acc, 0.f);
    }
    __syncthreads();
    for (int b = 0; b < BB; b++) {
        red[j] = hid[b * 512 + j] * fc2w[j];
        __syncthreads();
        for (int o = 256; o; o >>= 1) {
            if (j < o) red[j] += red[j + o];
            __syncthreads();
        }
        if (j == 0) out[b] = red[0] + fc2b[0];
        __syncthreads();
    }
}

// ---------------- host launcher ----------------
extern "C" void kernel_launch(void* const* d_in, const int* in_sizes, int n_in,
                              void* d_out, int out_size) {
    const float* x    = (const float*)d_in[0];
    const int*   ei   = (const int*)d_in[1];
    const float* ea   = (const float*)d_in[2];
    const float* wl0  = (const float*)d_in[3];
    const float* wr0  = (const float*)d_in[4];
    const float* we0  = (const float*)d_in[5];
    const float* att0 = (const float*)d_in[6];
    const float* b0   = (const float*)d_in[7];
    const float* wl1  = (const float*)d_in[8];
    const float* wr1  = (const float*)d_in[9];
    const float* we1  = (const float*)d_in[10];
    const float* att1 = (const float*)d_in[11];
    const float* b1   = (const float*)d_in[12];
    const float* wl2  = (const float*)d_in[13];
    const float* wr2  = (const float*)d_in[14];
    const float* we2  = (const float*)d_in[15];
    const float* att2 = (const float*)d_in[16];
    const float* b2   = (const float*)d_in[17];
    const float* wih  = (const float*)d_in[18];
    const float* whh  = (const float*)d_in[19];
    const float* bih  = (const float*)d_in[20];
    const float* bhh  = (const float*)d_in[21];
    const float* fc1w = (const float*)d_in[22];
    const float* fc1b = (const float*)d_in[23];
    const float* fc2w = (const float*)d_in[24];
    const float* fc2b = (const float*)d_in[25];

    void *p_xl, *p_xr, *p_hA, *p_hB, *p_deg, *p_h, *p_c;
    cudaGetSymbolAddress(&p_xl, g_xl);
    cudaGetSymbolAddress(&p_xr, g_xr);
    cudaGetSymbolAddress(&p_hA, g_hA);
    cudaGetSymbolAddress(&p_hB, g_hB);
    cudaGetSymbolAddress(&p_deg, g_deg);
    cudaGetSymbolAddress(&p_h, g_hstate);
    cudaGetSymbolAddress(&p_c, g_cstate);
    float* xl = (float*)p_xl;
    float* xr = (float*)p_xr;
    float* hA = (float*)p_hA;
    float* hB = (float*)p_hB;

    cudaMemsetAsync(p_deg, 0, NN * sizeof(int));
    cudaMemsetAsync(p_h, 0, BB * 256 * sizeof(float));
    cudaMemsetAsync(p_c, 0, BB * 256 * sizeof(float));

    k_ea_mean<<<1, 256>>>(ea);
    k_edges_prep<<<(ET + 255) / 256, 256>>>(ei);
    k_scan<<<1, 256>>>();
    k_scatter<<<(ET + 255) / 256, 256>>>();
    k_whht<<<1024, 256>>>(whh);

    const int M = GNUM * NN;  // 80000
    int aggr_blocks = (GNUM * NN + 7) / 8;  // 8 warps per block

    // ---- layer 0: 8 -> 128 (H=4, C=32) ----
    k_eep<<<(ET * 128 + 255) / 256, 256>>>(ea, we0, 128);
    k_gemm_n128<<<dim3(1, M / 128, 2), 256>>>(x, wl0, wr0, xl, xr, 8);
    k_aggr_fused<32><<<aggr_blocks, 256>>>(att0, b0, hA);

    // ---- layer 1: 128 -> 128 ----
    k_eep<<<(ET * 128 + 255) / 256, 256>>>(ea, we1, 128);
    k_gemm_n128<<<dim3(1, M / 128, 2), 256>>>(hA, wl1, wr1, xl, xr, 128);
    k_aggr_fused<32><<<aggr_blocks, 256>>>(att1, b1, hB);

    // ---- layer 2: 128 -> 32 (H=4, C=8) ----
    k_eep<<<(ET * 32 + 255) / 256, 256>>>(ea, we2, 32);
    k_gemm_n32<<<dim3(1, M / 128, 2), 256>>>(hB, wl2, wr2, xl, xr);
    k_aggr_fused<8><<<aggr_blocks, 256>>>(att2, b2, hA);  // hA = emb [40][64000]

    // ---- LSTM input projection ----
    k_init_gates<<<(GNUM * 1024 + 255) / 256, 256>>>(bih, bhh);
    cudaFuncSetAttribute(k_gates2, cudaFuncAttributeMaxDynamicSharedMemorySize,
                         GNUM * KC * sizeof(float));
    k_gates2<<<dim3(64000 / KC, 16), 128, GNUM * KC * sizeof(float)>>>(hA, wih);

    // ---- LSTM scan + head ----
    for (int t = 0; t < TT; t++) {
        k_lstm_gemm<<<8, 128>>>(t);
        k_lstm_update<<<1, 256>>>();
    }
    k_fc<<<1, 512>>>(fc1w, fc1b, fc2w, fc2b, (float*)d_out);
}

// round 3
// speedup vs baseline: 1.7603x; 1.3107x over previous
#include <cuda_runtime.h>
#include <cstdint>

#define GNUM 40     // B*T graphs
#define NN   2000   // nodes per graph
#define E0   16000  // original edges
#define ET   18000  // edges + self loops
#define TT   10
#define BB   4
#define KC   512    // k-chunk for gates GEMM
#define NCHUNK (64000 / KC)   // 125

// ---------------- scratch (device globals; no allocations allowed) ----------------
__device__ float  g_xl[GNUM * NN * 128];
__device__ float  g_xr[GNUM * NN * 128];
__device__ float  g_hA[GNUM * NN * 128];
__device__ float  g_hB[GNUM * NN * 128];
__device__ int    g_rowstart[NN + 1];
__device__ int    g_psrc[ET];              // CSR pos -> src node
__device__ float2 g_pea[ET];               // CSR pos -> edge attr (mean-filled self loops)
__device__ float  g_gates[GNUM * 1024];
__device__ float  g_part[NCHUNK * 1024 * GNUM];  // split-K partials (20.5 MB)
__device__ float  g_gacc[BB * 1024];
__device__ float  g_whht[256 * 1024];
__device__ float  g_cbuf[2][BB * 256];

// ---------------- fused prep: ea-mean, degree hist, scan, CSR scatter (1 block) --------
__global__ void __launch_bounds__(1024) k_prep_all(const int* __restrict__ ei,
                                                   const float* __restrict__ ea) {
    __shared__ int   sdeg[NN];      // degree, then reused as cursor
    __shared__ int   sscan[1024];
    __shared__ float r0[1024], r1[1024];
    __shared__ float2 smean;
    int t = threadIdx.x;

    // edge-attr mean
    float a = 0.f, b = 0.f;
    for (int e = t; e < E0; e += 1024) { a += ea[2 * e]; b += ea[2 * e + 1]; }
    r0[t] = a; r1[t] = b;
    for (int i = t; i < NN; i += 1024) sdeg[i] = 0;
    __syncthreads();
    for (int o = 512; o; o >>= 1) {
        if (t < o) { r0[t] += r0[t + o]; r1[t] += r1[t + o]; }
        __syncthreads();
    }
    if (t == 0) { smean.x = r0[0] / E0; smean.y = r1[0] / E0; }

    // degree histogram
    for (int e = t; e < ET; e += 1024) {
        int d = (e < E0) ? ei[E0 + e] : (e - E0);
        atomicAdd(&sdeg[d], 1);
    }
    __syncthreads();

    // exclusive scan (2 elems/thread + Hillis-Steele over 1024 partial sums)
    int i0 = 2 * t, i1 = 2 * t + 1;
    int v0 = (i0 < NN) ? sdeg[i0] : 0;
    int v1 = (i1 < NN) ? sdeg[i1] : 0;
    int tot = v0 + v1;
    sscan[t] = tot;
    __syncthreads();
    for (int off = 1; off < 1024; off <<= 1) {
        int x = (t >= off) ? sscan[t - off] : 0;
        __syncthreads();
        sscan[t] += x;
        __syncthreads();
    }
    int base = sscan[t] - tot;  // exclusive
    __syncthreads();            // done reading sdeg as degrees
    if (i0 < NN) { g_rowstart[i0] = base;      sdeg[i0] = base; }
    if (i1 < NN) { g_rowstart[i1] = base + v0; sdeg[i1] = base + v0; }
    if (t == 1023) g_rowstart[NN] = sscan[1023];
    __syncthreads();

    // scatter into CSR order
    float2 mn = smean;
    for (int e = t; e < ET; e += 1024) {
        int s, d;
        if (e < E0) { s = ei[e]; d = ei[E0 + e]; }
        else        { s = d = e - E0; }
        int pos = atomicAdd(&sdeg[d], 1);
        g_psrc[pos] = s;
        float2 v;
        if (e < E0) { v.x = ea[2 * e]; v.y = ea[2 * e + 1]; }
        else        v = mn;
        g_pea[pos] = v;
    }
}

// ---------------- whh transpose [1024,256] -> [256,1024]; also zero c buffers ----------
__global__ void k_whht(const float* __restrict__ whh) {
    int i = blockIdx.x * 256 + threadIdx.x;
    int j = i >> 8, k = i & 255;
    g_whht[k * 1024 + j] = whh[i];
    if (i < 2 * BB * 256) ((float*)g_cbuf)[i] = 0.f;
}

// ---------------- GEMM N=128: C[M,128] = A[M,K] @ B[K,128]; M%128==0, K%8==0 ------------
__global__ void __launch_bounds__(256) k_gemm_n128(const float* __restrict__ A,
                            const float* __restrict__ B0, const float* __restrict__ B1,
                            float* __restrict__ C0, float* __restrict__ C1, int K) {
    const float* B = blockIdx.z ? B1 : B0;
    float*       C = blockIdx.z ? C1 : C0;
    __shared__ float As[8][128];
    __shared__ float Bs[8][128];
    int tid = threadIdx.x;
    int m0 = blockIdx.y * 128;
    int arow = tid >> 1, acol4 = (tid & 1) * 4;
    int brow = tid >> 5, bcol = (tid & 31) * 4;
    int tx = tid & 15, ty = tid >> 4;
    const float* Ap = A + (size_t)(m0 + arow) * K + acol4;
    float4 av = *(const float4*)Ap;
    float4 bv = *(const float4*)(B + (size_t)brow * 128 + bcol);
    float acc[8][8] = {};
    for (int k0 = 0; k0 < K; k0 += 8) {
        As[acol4 + 0][arow] = av.x; As[acol4 + 1][arow] = av.y;
        As[acol4 + 2][arow] = av.z; As[acol4 + 3][arow] = av.w;
        *(float4*)&Bs[brow][bcol] = bv;
        __syncthreads();
        if (k0 + 8 < K) {
            av = *(const float4*)(Ap + k0 + 8);
            bv = *(const float4*)(B + (size_t)(k0 + 8 + brow) * 128 + bcol);
        }
#pragma unroll
        for (int kk = 0; kk < 8; kk++) {
            float a[8], b[8];
            *(float4*)a       = *(const float4*)&As[kk][ty * 8];
            *(float4*)(a + 4) = *(const float4*)&As[kk][ty * 8 + 4];
            *(float4*)b       = *(const float4*)&Bs[kk][tx * 8];
            *(float4*)(b + 4) = *(const float4*)&Bs[kk][tx * 8 + 4];
#pragma unroll
            for (int i = 0; i < 8; i++)
#pragma unroll
                for (int j = 0; j < 8; j++) acc[i][j] += a[i] * b[j];
        }
        __syncthreads();
    }
#pragma unroll
    for (int i = 0; i < 8; i++) {
        float* cp = C + (size_t)(m0 + ty * 8 + i) * 128 + tx * 8;
        *(float4*)cp       = *(float4*)&acc[i][0];
        *(float4*)(cp + 4) = *(float4*)&acc[i][4];
    }
}

// ---------------- GEMM N=32: C[M,32] = A[M,128] @ B[128,32] ----------------
__global__ void __launch_bounds__(256) k_gemm_n32(const float* __restrict__ A,
                           const float* __restrict__ B0, const float* __restrict__ B1,
                           float* __restrict__ C0, float* __restrict__ C1) {
    const float* B = blockIdx.z ? B1 : B0;
    float*       C = blockIdx.z ? C1 : C0;
    __shared__ float As[16][128];
    __shared__ float Bs[16][32];
    int tid = threadIdx.x;
    int m0 = blockIdx.y * 128;
    int tx = tid & 15, ty = tid >> 4;
    float acc[8][2] = {};
    for (int k0 = 0; k0 < 128; k0 += 16) {
#pragma unroll
        for (int it = 0; it < 2; it++) {
            int idx = tid + it * 256;
            int ar = idx >> 2, ac4 = (idx & 3) * 4;
            float4 av = *(const float4*)(A + (size_t)(m0 + ar) * 128 + k0 + ac4);
            As[ac4 + 0][ar] = av.x; As[ac4 + 1][ar] = av.y;
            As[ac4 + 2][ar] = av.z; As[ac4 + 3][ar] = av.w;
        }
        if (tid < 128) {
            int br = tid >> 3, bc = (tid & 7) * 4;
            *(float4*)&Bs[br][bc] = *(const float4*)(B + (size_t)(k0 + br) * 32 + bc);
        }
        __syncthreads();
#pragma unroll
        for (int kk = 0; kk < 16; kk++) {
            float a[8];
            *(float4*)a       = *(const float4*)&As[kk][ty * 8];
            *(float4*)(a + 4) = *(const float4*)&As[kk][ty * 8 + 4];
            float b0v = Bs[kk][tx * 2], b1v = Bs[kk][tx * 2 + 1];
#pragma unroll
            for (int i = 0; i < 8; i++) { acc[i][0] += a[i] * b0v; acc[i][1] += a[i] * b1v; }
        }
        __syncthreads();
    }
#pragma unroll
    for (int i = 0; i < 8; i++) {
        float2 v; v.x = acc[i][0]; v.y = acc[i][1];
        *(float2*)(C + (size_t)(m0 + ty * 8 + i) * 32 + tx * 2) = v;
    }
}

// ---------------- fused logits + softmax + aggregation; ee recomputed on the fly --------
template <int C>
__global__ void k_aggr_fused(const float* __restrict__ att, const float* __restrict__ We,
                             const float* __restrict__ bias, float* __restrict__ out) {
    int gid  = blockIdx.x * (blockDim.x >> 5) + (threadIdx.x >> 5);
    int lane = threadIdx.x & 31;
    if (gid >= GNUM * NN) return;
    int g = gid / NN, d = gid - g * NN;
    int rs = g_rowstart[d], re = g_rowstart[d + 1];
    if (C == 32) {
        const float* xlg = g_xl + (size_t)g * NN * 128;
        const float* xrr = g_xr + ((size_t)g * NN + d) * 128;
        float xrv[4], attv[4], we0v[4], we1v[4], acc[4] = {}, den[4] = {};
#pragma unroll
        for (int h = 0; h < 4; h++) {
            int j = h * 32 + lane;
            xrv[h] = xrr[j]; attv[h] = att[j];
            we0v[h] = We[j]; we1v[h] = We[128 + j];
        }
#pragma unroll 2
        for (int i = rs; i < re; i++) {
            int s = g_psrc[i];
            float2 a = g_pea[i];
            const float* xls = xlg + (size_t)s * 128;
            float xlv[4], vv[4];
#pragma unroll
            for (int h = 0; h < 4; h++) xlv[h] = xls[h * 32 + lane];
#pragma unroll
            for (int h = 0; h < 4; h++) {
                float v = xlv[h] + xrv[h] + a.x * we0v[h] + a.y * we1v[h];
                v = v > 0.f ? v : 0.2f * v;
                vv[h] = v * attv[h];
            }
#pragma unroll
            for (int o = 16; o; o >>= 1) {
#pragma unroll
                for (int h = 0; h < 4; h++) vv[h] += __shfl_xor_sync(0xffffffffu, vv[h], o);
            }
#pragma unroll
            for (int h = 0; h < 4; h++) {
                float p = __expf(vv[h]);
                den[h] += p; acc[h] += p * xlv[h];
            }
        }
        float* op = out + ((size_t)g * NN + d) * 128;
#pragma unroll
        for (int h = 0; h < 4; h++)
            op[h * 32 + lane] = fmaxf(acc[h] / (den[h] + 1e-16f) + bias[h * 32 + lane], 0.f);
    } else {  // C == 8, HC = 32
        const float* xlg = g_xl + (size_t)g * NN * 32;
        float xrv = g_xr[((size_t)g * NN + d) * 32 + lane];
        float attv = att[lane];
        float we0v = We[lane], we1v = We[32 + lane];
        float acc = 0.f, den = 0.f;
#pragma unroll 2
        for (int i = rs; i < re; i++) {
            int s = g_psrc[i];
            float2 a = g_pea[i];
            float xlv = xlg[(size_t)s * 32 + lane];
            float v = xlv + xrv + a.x * we0v + a.y * we1v;
            v = v > 0.f ? v : 0.2f * v;
            v *= attv;
            v += __shfl_xor_sync(0xffffffffu, v, 4);
            v += __shfl_xor_sync(0xffffffffu, v, 2);
            v += __shfl_xor_sync(0xffffffffu, v, 1);
            float p = __expf(v);
            den += p; acc += p * xlv;
        }
        out[((size_t)g * NN + d) * 32 + lane] =
            fmaxf(acc / (den + 1e-16f) + bias[lane], 0.f);
    }
}

// ---------------- LSTM input projection, stage 1: split-K partials ----------------
__global__ void __launch_bounds__(128)
k_gates2(const float* __restrict__ emb, const float* __restrict__ wih) {
    extern __shared__ float es[];  // [GNUM][KC] = 80 KB
    __shared__ float sout[16][GNUM];
    int chunk = blockIdx.x;
    int k0 = chunk * KC;
    int tid = threadIdx.x, warp = tid >> 5, lane = tid & 31;
    const float4* e4g = (const float4*)emb;
    float4* es4 = (float4*)es;
    for (int idx = tid; idx < GNUM * KC / 4; idx += 128) {
        int b = idx / (KC / 4), kq = idx - b * (KC / 4);
        es4[idx] = e4g[(size_t)b * 16000 + (k0 >> 2) + kq];
    }
    __syncthreads();
#pragma unroll 1
    for (int pass = 0; pass < 4; pass++) {
        int j0 = blockIdx.y * 64 + pass * 16 + warp * 4;
        float acc[4][GNUM];
#pragma unroll
        for (int jj = 0; jj < 4; jj++)
#pragma unroll
            for (int b = 0; b < GNUM; b++) acc[jj][b] = 0.f;
#pragma unroll 2
        for (int s = 0; s < KC / 128; s++) {
            float4 w4[4];
#pragma unroll
            for (int jj = 0; jj < 4; jj++)
                w4[jj] = *(const float4*)(wih + (size_t)(j0 + jj) * 64000 + k0 + s * 128 + lane * 4);
#pragma unroll
            for (int b = 0; b < GNUM; b++) {
                float4 ev = *(const float4*)(es + b * KC + s * 128 + lane * 4);
#pragma unroll
                for (int jj = 0; jj < 4; jj++) {
                    acc[jj][b] += w4[jj].x * ev.x;
                    acc[jj][b] += w4[jj].y * ev.y;
                    acc[jj][b] += w4[jj].z * ev.z;
                    acc[jj][b] += w4[jj].w * ev.w;
                }
            }
        }
#pragma unroll
        for (int jj = 0; jj < 4; jj++)
#pragma unroll
            for (int b = 0; b < GNUM; b++) {
                float v = acc[jj][b];
                v += __shfl_xor_sync(0xffffffffu, v, 16);
                v += __shfl_xor_sync(0xffffffffu, v, 8);
                v += __shfl_xor_sync(0xffffffffu, v, 4);
                v += __shfl_xor_sync(0xffffffffu, v, 2);
                v += __shfl_xor_sync(0xffffffffu, v, 1);
                if (lane == 0) sout[warp * 4 + jj][b] = v;
            }
        __syncthreads();
        int jbase = blockIdx.y * 64 + pass * 16;
        for (int idx = tid; idx < 16 * GNUM; idx += 128) {
            int jr = idx / GNUM, b = idx - jr * GNUM;
            g_part[(size_t)chunk * 1024 * GNUM + (size_t)(jbase + jr) * GNUM + b] = sout[jr][b];
        }
        __syncthreads();
    }
}

// ---------------- stage 2: reduce partials + biases -> g_gates ----------------
__global__ void k_gates_reduce(const float* __restrict__ bih, const float* __restrict__ bhh) {
    int i = blockIdx.x * blockDim.x + threadIdx.x;  // i = j*40 + gi
    if (i >= 1024 * GNUM) return;
    int j = i / GNUM, gi = i - j * GNUM;
    float s = bih[j] + bhh[j];
    for (int c = 0; c < NCHUNK; c++) s += g_part[(size_t)c * 1024 * GNUM + i];
    g_gates[gi * 1024 + j] = s;
}

// ---------------- LSTM: fused update + gate GEMM per step ----------------
__device__ __forceinline__ float sigf(float x) { return 1.f / (1.f + __expf(-x)); }
__device__ __forceinline__ float tanhfast(float x) { return 1.f - 2.f / (__expf(2.f * x) + 1.f); }

__global__ void __launch_bounds__(128) k_lstm_step(int t) {  // grid 8 x 128
    __shared__ float hs[BB * 256];
    int tid = threadIdx.x;
    int j = blockIdx.x * 128 + tid;
    if (t == 0) {
        for (int i = tid; i < BB * 256; i += 128) hs[i] = 0.f;
    } else {
        const float* cprev = g_cbuf[t & 1];
        float* cnew = g_cbuf[(t + 1) & 1];
        for (int idx = tid; idx < BB * 256; idx += 128) {
            int b = idx >> 8, k = idx & 255;
            const float* ga = g_gacc + b * 1024;
            float iv = ga[k], fv = ga[256 + k], gv = ga[512 + k], ov = ga[768 + k];
            float c = sigf(fv) * cprev[idx] + sigf(iv) * tanhfast(gv);
            if (blockIdx.x == 0) cnew[idx] = c;
            hs[idx] = sigf(ov) * tanhfast(c);
        }
    }
    __syncthreads();
    float acc[BB];
#pragma unroll
    for (int b = 0; b < BB; b++) acc[b] = g_gates[(size_t)(b * TT + t) * 1024 + j];
#pragma unroll 4
    for (int k = 0; k < 256; k++) {
        float w = g_whht[k * 1024 + j];
#pragma unroll
        for (int b = 0; b < BB; b++) acc[b] += w * hs[b * 256 + k];
    }
#pragma unroll
    for (int b = 0; b < BB; b++) g_gacc[b * 1024 + j] = acc[b];
}

// ---------------- final: compute h_9, relu, fc1, relu, fc2 ----------------
__global__ void __launch_bounds__(512) k_fc(const float* __restrict__ fc1w,
                     const float* __restrict__ fc1b,
                     const float* __restrict__ fc2w, const float* __restrict__ fc2b,
                     float* __restrict__ out) {
    __shared__ float last[BB * 256];
    __shared__ float hid[BB * 512];
    __shared__ float red[512];
    int j = threadIdx.x;  // 512 threads
    const float* c8 = g_cbuf[0];  // written by step t=9 at parity (9+1)&1 = 0
    for (int idx = j; idx < BB * 256; idx += 512) {
        int b = idx >> 8, k = idx & 255;
        const float* ga = g_gacc + b * 1024;
        float iv = ga[k], fv = ga[256 + k], gv = ga[512 + k], ov = ga[768 + k];
        float c = sigf(fv) * c8[idx] + sigf(iv) * tanhfast(gv);
        last[idx] = fmaxf(sigf(ov) * tanhfast(c), 0.f);
    }
    __syncthreads();
    for (int b = 0; b < BB; b++) {
        float acc = fc1b[j];
        for (int k = 0; k < 256; k++) acc += last[b * 256 + k] * fc1w[k * 512 + j];
        hid[b * 512 + j] = fmaxf(acc, 0.f);
    }
    __syncthreads();
    for (int b = 0; b < BB; b++) {
        red[j] = hid[b * 512 + j] * fc2w[j];
        __syncthreads();
        for (int o = 256; o; o >>= 1) {
            if (j < o) red[j] += red[j + o];
            __syncthreads();
        }
        if (j == 0) out[b] = red[0] + fc2b[0];
        __syncthreads();
    }
}

// ---------------- host launcher ----------------
extern "C" void kernel_launch(void* const* d_in, const int* in_sizes, int n_in,
                              void* d_out, int out_size) {
    const float* x    = (const float*)d_in[0];
    const int*   ei   = (const int*)d_in[1];
    const float* ea   = (const float*)d_in[2];
    const float* wl0  = (const float*)d_in[3];
    const float* wr0  = (const float*)d_in[4];
    const float* we0  = (const float*)d_in[5];
    const float* att0 = (const float*)d_in[6];
    const float* b0   = (const float*)d_in[7];
    const float* wl1  = (const float*)d_in[8];
    const float* wr1  = (const float*)d_in[9];
    const float* we1  = (const float*)d_in[10];
    const float* att1 = (const float*)d_in[11];
    const float* b1   = (const float*)d_in[12];
    const float* wl2  = (const float*)d_in[13];
    const float* wr2  = (const float*)d_in[14];
    const float* we2  = (const float*)d_in[15];
    const float* att2 = (const float*)d_in[16];
    const float* b2   = (const float*)d_in[17];
    const float* wih  = (const float*)d_in[18];
    const float* whh  = (const float*)d_in[19];
    const float* bih  = (const float*)d_in[20];
    const float* bhh  = (const float*)d_in[21];
    const float* fc1w = (const float*)d_in[22];
    const float* fc1b = (const float*)d_in[23];
    const float* fc2w = (const float*)d_in[24];
    const float* fc2b = (const float*)d_in[25];

    void *p_xl, *p_xr, *p_hA, *p_hB;
    cudaGetSymbolAddress(&p_xl, g_xl);
    cudaGetSymbolAddress(&p_xr, g_xr);
    cudaGetSymbolAddress(&p_hA, g_hA);
    cudaGetSymbolAddress(&p_hB, g_hB);
    float* xl = (float*)p_xl;
    float* xr = (float*)p_xr;
    float* hA = (float*)p_hA;
    float* hB = (float*)p_hB;

    const int M = GNUM * NN;  // 80000
    int aggr_blocks = (GNUM * NN + 7) / 8;  // 8 warps per block

    k_prep_all<<<1, 1024>>>(ei, ea);
    k_whht<<<1024, 256>>>(whh);

    // ---- layer 0: 8 -> 128 ----
    k_gemm_n128<<<dim3(1, M / 128, 2), 256>>>(x, wl0, wr0, xl, xr, 8);
    k_aggr_fused<32><<<aggr_blocks, 256>>>(att0, we0, b0, hA);

    // ---- layer 1: 128 -> 128 ----
    k_gemm_n128<<<dim3(1, M / 128, 2), 256>>>(hA, wl1, wr1, xl, xr, 128);
    k_aggr_fused<32><<<aggr_blocks, 256>>>(att1, we1, b1, hB);

    // ---- layer 2: 128 -> 32 ----
    k_gemm_n32<<<dim3(1, M / 128, 2), 256>>>(hB, wl2, wr2, xl, xr);
    k_aggr_fused<8><<<aggr_blocks, 256>>>(att2, we2, b2, hA);  // hA = emb [40][64000]

    // ---- LSTM input projection (split-K, no atomics) ----
    cudaFuncSetAttribute(k_gates2, cudaFuncAttributeMaxDynamicSharedMemorySize,
                         GNUM * KC * sizeof(float));
    k_gates2<<<dim3(NCHUNK, 16), 128, GNUM * KC * sizeof(float)>>>(hA, wih);
    k_gates_reduce<<<(1024 * GNUM + 255) / 256, 256>>>(bih, bhh);

    // ---- LSTM scan (fused update+gemm) + head ----
    for (int t = 0; t < TT; t++) k_lstm_step<<<8, 128>>>(t);
    k_fc<<<1, 512>>>(fc1w, fc1b, fc2w, fc2b, (float*)d_out);
}

// round 4
// speedup vs baseline: 1.7923x; 1.0182x over previous
#include <cuda_runtime.h>
#include <cstdint>

#define GNUM 40     // B*T graphs
#define NN   2000   // nodes per graph
#define E0   16000  // original edges
#define ET   18000  // edges + self loops
#define TT   10
#define BB   4
#define KC   512    // k-chunk for gates GEMM
#define NCHUNK (64000 / KC)   // 125

// ---------------- scratch (device globals; no allocations allowed) ----------------
__device__ float  g_xl[GNUM * NN * 128];
__device__ float  g_xr[GNUM * NN * 128];
__device__ float  g_hA[GNUM * NN * 128];
__device__ float  g_hB[GNUM * NN * 128];
__device__ int    g_rowstart[NN + 1];
__device__ int    g_psrc[ET];              // CSR pos -> src node
__device__ float2 g_pea[ET];               // CSR pos -> edge attr (mean-filled self loops)
__device__ float  g_gates[GNUM * 1024];
__device__ float  g_part[NCHUNK * 1024 * GNUM];  // split-K partials (20.5 MB)
__device__ float  g_gacc[BB * 1024];
__device__ float  g_whht[256 * 1024];
__device__ float  g_cbuf[2][BB * 256];

// ---------------- fused prep: ea-mean, degree hist, scan, CSR scatter (1 block) --------
__global__ void __launch_bounds__(1024) k_prep_all(const int* __restrict__ ei,
                                                   const float* __restrict__ ea) {
    __shared__ int   sdeg[NN];      // degree, then reused as cursor
    __shared__ int   sscan[1024];
    __shared__ float r0[1024], r1[1024];
    __shared__ float2 smean;
    int t = threadIdx.x;

    // edge-attr mean
    float a = 0.f, b = 0.f;
    for (int e = t; e < E0; e += 1024) { a += ea[2 * e]; b += ea[2 * e + 1]; }
    r0[t] = a; r1[t] = b;
    for (int i = t; i < NN; i += 1024) sdeg[i] = 0;
    __syncthreads();
    for (int o = 512; o; o >>= 1) {
        if (t < o) { r0[t] += r0[t + o]; r1[t] += r1[t + o]; }
        __syncthreads();
    }
    if (t == 0) { smean.x = r0[0] / E0; smean.y = r1[0] / E0; }

    // degree histogram
    for (int e = t; e < ET; e += 1024) {
        int d = (e < E0) ? ei[E0 + e] : (e - E0);
        atomicAdd(&sdeg[d], 1);
    }
    __syncthreads();

    // exclusive scan (2 elems/thread + Hillis-Steele over 1024 partial sums)
    int i0 = 2 * t, i1 = 2 * t + 1;
    int v0 = (i0 < NN) ? sdeg[i0] : 0;
    int v1 = (i1 < NN) ? sdeg[i1] : 0;
    int tot = v0 + v1;
    sscan[t] = tot;
    __syncthreads();
    for (int off = 1; off < 1024; off <<= 1) {
        int x = (t >= off) ? sscan[t - off] : 0;
        __syncthreads();
        sscan[t] += x;
        __syncthreads();
    }
    int base = sscan[t] - tot;  // exclusive
    __syncthreads();            // done reading sdeg as degrees
    if (i0 < NN) { g_rowstart[i0] = base;      sdeg[i0] = base; }
    if (i1 < NN) { g_rowstart[i1] = base + v0; sdeg[i1] = base + v0; }
    if (t == 1023) g_rowstart[NN] = sscan[1023];
    __syncthreads();

    // scatter into CSR order
    float2 mn = smean;
    for (int e = t; e < ET; e += 1024) {
        int s, d;
        if (e < E0) { s = ei[e]; d = ei[E0 + e]; }
        else        { s = d = e - E0; }
        int pos = atomicAdd(&sdeg[d], 1);
        g_psrc[pos] = s;
        float2 v;
        if (e < E0) { v.x = ea[2 * e]; v.y = ea[2 * e + 1]; }
        else        v = mn;
        g_pea[pos] = v;
    }
}

// ---------------- whh transpose [1024,256] -> [256,1024]; also zero c buffers ----------
__global__ void k_whht(const float* __restrict__ whh) {
    int i = blockIdx.x * 256 + threadIdx.x;
    int j = i >> 8, k = i & 255;
    g_whht[k * 1024 + j] = whh[i];
    if (i < 2 * BB * 256) ((float*)g_cbuf)[i] = 0.f;
}

// ---------------- GEMM N=128: C[M,128] = A[M,K] @ B[K,128]; M%128==0, K%8==0 ------------
__global__ void __launch_bounds__(256) k_gemm_n128(const float* __restrict__ A,
                            const float* __restrict__ B0, const float* __restrict__ B1,
                            float* __restrict__ C0, float* __restrict__ C1, int K) {
    const float* B = blockIdx.z ? B1 : B0;
    float*       C = blockIdx.z ? C1 : C0;
    __shared__ float As[8][128];
    __shared__ float Bs[8][128];
    int tid = threadIdx.x;
    int m0 = blockIdx.y * 128;
    int arow = tid >> 1, acol4 = (tid & 1) * 4;
    int brow = tid >> 5, bcol = (tid & 31) * 4;
    int tx = tid & 15, ty = tid >> 4;
    const float* Ap = A + (size_t)(m0 + arow) * K + acol4;
    float4 av = *(const float4*)Ap;
    float4 bv = *(const float4*)(B + (size_t)brow * 128 + bcol);
    float acc[8][8] = {};
    for (int k0 = 0; k0 < K; k0 += 8) {
        As[acol4 + 0][arow] = av.x; As[acol4 + 1][arow] = av.y;
        As[acol4 + 2][arow] = av.z; As[acol4 + 3][arow] = av.w;
        *(float4*)&Bs[brow][bcol] = bv;
        __syncthreads();
        if (k0 + 8 < K) {
            av = *(const float4*)(Ap + k0 + 8);
            bv = *(const float4*)(B + (size_t)(k0 + 8 + brow) * 128 + bcol);
        }
#pragma unroll
        for (int kk = 0; kk < 8; kk++) {
            float a[8], b[8];
            *(float4*)a       = *(const float4*)&As[kk][ty * 8];
            *(float4*)(a + 4) = *(const float4*)&As[kk][ty * 8 + 4];
            *(float4*)b       = *(const float4*)&Bs[kk][tx * 8];
            *(float4*)(b + 4) = *(const float4*)&Bs[kk][tx * 8 + 4];
#pragma unroll
            for (int i = 0; i < 8; i++)
#pragma unroll
                for (int j = 0; j < 8; j++) acc[i][j] += a[i] * b[j];
        }
        __syncthreads();
    }
#pragma unroll
    for (int i = 0; i < 8; i++) {
        float* cp = C + (size_t)(m0 + ty * 8 + i) * 128 + tx * 8;
        *(float4*)cp       = *(float4*)&acc[i][0];
        *(float4*)(cp + 4) = *(float4*)&acc[i][4];
    }
}

// ---------------- GEMM N=32: C[M,32] = A[M,128] @ B[128,32] ----------------
__global__ void __launch_bounds__(256) k_gemm_n32(const float* __restrict__ A,
                           const float* __restrict__ B0, const float* __restrict__ B1,
                           float* __restrict__ C0, float* __restrict__ C1) {
    const float* B = blockIdx.z ? B1 : B0;
    float*       C = blockIdx.z ? C1 : C0;
    __shared__ float As[16][128];
    __shared__ float Bs[16][32];
    int tid = threadIdx.x;
    int m0 = blockIdx.y * 128;
    int tx = tid & 15, ty = tid >> 4;
    float acc[8][2] = {};
    for (int k0 = 0; k0 < 128; k0 += 16) {
#pragma unroll
        for (int it = 0; it < 2; it++) {
            int idx = tid + it * 256;
            int ar = idx >> 2, ac4 = (idx & 3) * 4;
            float4 av = *(const float4*)(A + (size_t)(m0 + ar) * 128 + k0 + ac4);
            As[ac4 + 0][ar] = av.x; As[ac4 + 1][ar] = av.y;
            As[ac4 + 2][ar] = av.z; As[ac4 + 3][ar] = av.w;
        }
        if (tid < 128) {
            int br = tid >> 3, bc = (tid & 7) * 4;
            *(float4*)&Bs[br][bc] = *(const float4*)(B + (size_t)(k0 + br) * 32 + bc);
        }
        __syncthreads();
#pragma unroll
        for (int kk = 0; kk < 16; kk++) {
            float a[8];
            *(float4*)a       = *(const float4*)&As[kk][ty * 8];
            *(float4*)(a + 4) = *(const float4*)&As[kk][ty * 8 + 4];
            float b0v = Bs[kk][tx * 2], b1v = Bs[kk][tx * 2 + 1];
#pragma unroll
            for (int i = 0; i < 8; i++) { acc[i][0] += a[i] * b0v; acc[i][1] += a[i] * b1v; }
        }
        __syncthreads();
    }
#pragma unroll
    for (int i = 0; i < 8; i++) {
        float2 v; v.x = acc[i][0]; v.y = acc[i][1];
        *(float2*)(C + (size_t)(m0 + ty * 8 + i) * 32 + tx * 2) = v;
    }
}

// ---------------- fused logits + softmax + aggregation; cheap 4-head reduction ----------
// Heads land in lane groups: h0 -> lanes with bits(16,8)=00 (base 0), h1 -> 10 (base 16),
// h2 -> 01 (base 8), h3 -> 11 (base 24).
template <int C>
__global__ void k_aggr_fused(const float* __restrict__ att, const float* __restrict__ We,
                             const float* __restrict__ bias, float* __restrict__ out) {
    int gid  = blockIdx.x * (blockDim.x >> 5) + (threadIdx.x >> 5);
    int lane = threadIdx.x & 31;
    if (gid >= GNUM * NN) return;
    int g = gid / NN, d = gid - g * NN;
    int rs = g_rowstart[d], re = g_rowstart[d + 1];
    if (C == 32) {
        const float* xlg = g_xl + (size_t)g * NN * 128;
        const float* xrr = g_xr + ((size_t)g * NN + d) * 128;
        float xrv[4], attv[4], we0v[4], we1v[4], acc[4] = {};
        float den = 0.f;   // per-lane-group denominator (head h(lane))
        bool hi16 = (lane & 16) != 0, hi8 = (lane & 8) != 0;
#pragma unroll
        for (int h = 0; h < 4; h++) {
            int j = h * 32 + lane;
            xrv[h] = xrr[j]; attv[h] = att[j];
            we0v[h] = We[j]; we1v[h] = We[128 + j];
        }
#pragma unroll 2
        for (int i = rs; i < re; i++) {
            int s = g_psrc[i];
            float2 a = g_pea[i];
            const float* xls = xlg + (size_t)s * 128;
            float xlv[4], vv[4];
#pragma unroll
            for (int h = 0; h < 4; h++) xlv[h] = xls[h * 32 + lane];
#pragma unroll
            for (int h = 0; h < 4; h++) {
                float v = xlv[h] + xrv[h] + a.x * we0v[h] + a.y * we1v[h];
                v = v > 0.f ? v : 0.2f * v;
                vv[h] = v * attv[h];
            }
            // stage 1: merge head pairs across xor-16
            float m01 = hi16 ? vv[1] : vv[0];
            float o01 = hi16 ? vv[0] : vv[1];
            m01 += __shfl_xor_sync(0xffffffffu, o01, 16);
            float m23 = hi16 ? vv[3] : vv[2];
            float o23 = hi16 ? vv[2] : vv[3];
            m23 += __shfl_xor_sync(0xffffffffu, o23, 16);
            // stage 2: merge across xor-8
            float q  = hi8 ? m23 : m01;
            float rr = hi8 ? m01 : m23;
            q += __shfl_xor_sync(0xffffffffu, rr, 8);
            // stage 3: butterfly within group of 8
            q += __shfl_xor_sync(0xffffffffu, q, 4);
            q += __shfl_xor_sync(0xffffffffu, q, 2);
            q += __shfl_xor_sync(0xffffffffu, q, 1);
            float p = __expf(q);   // p of this lane's group head
            den += p;
            float p0 = __shfl_sync(0xffffffffu, p, 0);
            float p1 = __shfl_sync(0xffffffffu, p, 16);
            float p2 = __shfl_sync(0xffffffffu, p, 8);
            float p3 = __shfl_sync(0xffffffffu, p, 24);
            acc[0] += p0 * xlv[0];
            acc[1] += p1 * xlv[1];
            acc[2] += p2 * xlv[2];
            acc[3] += p3 * xlv[3];
        }
        float dh[4];
        dh[0] = __shfl_sync(0xffffffffu, den, 0);
        dh[1] = __shfl_sync(0xffffffffu, den, 16);
        dh[2] = __shfl_sync(0xffffffffu, den, 8);
        dh[3] = __shfl_sync(0xffffffffu, den, 24);
        float* op = out + ((size_t)g * NN + d) * 128;
#pragma unroll
        for (int h = 0; h < 4; h++)
            op[h * 32 + lane] = fmaxf(acc[h] / (dh[h] + 1e-16f) + bias[h * 32 + lane], 0.f);
    } else {  // C == 8, HC = 32
        const float* xlg = g_xl + (size_t)g * NN * 32;
        float xrv = g_xr[((size_t)g * NN + d) * 32 + lane];
        float attv = att[lane];
        float we0v = We[lane], we1v = We[32 + lane];
        float acc = 0.f, den = 0.f;
#pragma unroll 2
        for (int i = rs; i < re; i++) {
            int s = g_psrc[i];
            float2 a = g_pea[i];
            float xlv = xlg[(size_t)s * 32 + lane];
            float v = xlv + xrv + a.x * we0v + a.y * we1v;
            v = v > 0.f ? v : 0.2f * v;
            v *= attv;
            v += __shfl_xor_sync(0xffffffffu, v, 4);
            v += __shfl_xor_sync(0xffffffffu, v, 2);
            v += __shfl_xor_sync(0xffffffffu, v, 1);
            float p = __expf(v);
            den += p; acc += p * xlv;
        }
        out[((size_t)g * NN + d) * 32 + lane] =
            fmaxf(acc / (den + 1e-16f) + bias[lane], 0.f);
    }
}

// ---------------- LSTM input projection, stage 1: split-K partials ----------------
// 256 threads = 8 warps; warp owns 8 j's; graph dim tiled 8 x 5 -> acc[8][5] (40 regs).
__global__ void __launch_bounds__(256)
k_gates2(const float* __restrict__ emb, const float* __restrict__ wih) {
    extern __shared__ float es[];            // [GNUM][KC] = 80 KB
    __shared__ float sout[64][GNUM];         // 10 KB
    int chunk = blockIdx.x;
    int k0 = chunk * KC;
    int tid = threadIdx.x, warp = tid >> 5, lane = tid & 31;
    const float4* e4g = (const float4*)emb;
    float4* es4 = (float4*)es;
    for (int idx = tid; idx < GNUM * KC / 4; idx += 256) {
        int b = idx / (KC / 4), kq = idx - b * (KC / 4);
        es4[idx] = e4g[(size_t)b * 16000 + (k0 >> 2) + kq];
    }
    __syncthreads();
    int j0 = blockIdx.y * 64 + warp * 8;
#pragma unroll 1
    for (int bt = 0; bt < 8; bt++) {
        float acc[8][5];
#pragma unroll
        for (int jj = 0; jj < 8; jj++)
#pragma unroll
            for (int bb = 0; bb < 5; bb++) acc[jj][bb] = 0.f;
#pragma unroll 1
        for (int s = 0; s < KC / 128; s++) {
            float4 w4[8];
#pragma unroll
            for (int jj = 0; jj < 8; jj++)
                w4[jj] = *(const float4*)(wih + (size_t)(j0 + jj) * 64000 + k0 + s * 128 + lane * 4);
#pragma unroll
            for (int bb = 0; bb < 5; bb++) {
                int b = bt * 5 + bb;
                float4 ev = *(const float4*)(es + b * KC + s * 128 + lane * 4);
#pragma unroll
                for (int jj = 0; jj < 8; jj++) {
                    acc[jj][bb] += w4[jj].x * ev.x;
                    acc[jj][bb] += w4[jj].y * ev.y;
                    acc[jj][bb] += w4[jj].z * ev.z;
                    acc[jj][bb] += w4[jj].w * ev.w;
                }
            }
        }
#pragma unroll
        for (int jj = 0; jj < 8; jj++)
#pragma unroll
            for (int bb = 0; bb < 5; bb++) {
                float v = acc[jj][bb];
                v += __shfl_xor_sync(0xffffffffu, v, 16);
                v += __shfl_xor_sync(0xffffffffu, v, 8);
                v += __shfl_xor_sync(0xffffffffu, v, 4);
                v += __shfl_xor_sync(0xffffffffu, v, 2);
                v += __shfl_xor_sync(0xffffffffu, v, 1);
                if (lane == 0) sout[warp * 8 + jj][bt * 5 + bb] = v;
            }
    }
    __syncthreads();
    // coalesced store: flat index over [64 j][40 b]
    for (int idx = tid; idx < 64 * GNUM; idx += 256) {
        int jr = idx / GNUM, b = idx - jr * GNUM;
        g_part[(size_t)chunk * 1024 * GNUM + (size_t)(blockIdx.y * 64 + jr) * GNUM + b] =
            sout[jr][b];
    }
}

// ---------------- stage 2: reduce partials + biases -> g_gates ----------------
__global__ void k_gates_reduce(const float* __restrict__ bih, const float* __restrict__ bhh) {
    int i = blockIdx.x * blockDim.x + threadIdx.x;  // i = j*40 + gi
    if (i >= 1024 * GNUM) return;
    int j = i / GNUM, gi = i - j * GNUM;
    float s = bih[j] + bhh[j];
    for (int c = 0; c < NCHUNK; c++) s += g_part[(size_t)c * 1024 * GNUM + i];
    g_gates[gi * 1024 + j] = s;
}

// ---------------- LSTM: fused update + gate GEMM per step ----------------
__device__ __forceinline__ float sigf(float x) { return 1.f / (1.f + __expf(-x)); }
__device__ __forceinline__ float tanhfast(float x) { return 1.f - 2.f / (__expf(2.f * x) + 1.f); }

__global__ void __launch_bounds__(128) k_lstm_step(int t) {  // grid 8 x 128
    __shared__ float hs[BB * 256];
    int tid = threadIdx.x;
    int j = blockIdx.x * 128 + tid;
    if (t == 0) {
        for (int i = tid; i < BB * 256; i += 128) hs[i] = 0.f;
    } else {
        const float* cprev = g_cbuf[t & 1];
        float* cnew = g_cbuf[(t + 1) & 1];
        for (int idx = tid; idx < BB * 256; idx += 128) {
            int b = idx >> 8, k = idx & 255;
            const float* ga = g_gacc + b * 1024;
            float iv = ga[k], fv = ga[256 + k], gv = ga[512 + k], ov = ga[768 + k];
            float c = sigf(fv) * cprev[idx] + sigf(iv) * tanhfast(gv);
            if (blockIdx.x == 0) cnew[idx] = c;
            hs[idx] = sigf(ov) * tanhfast(c);
        }
    }
    __syncthreads();
    float acc[BB];
#pragma unroll
    for (int b = 0; b < BB; b++) acc[b] = g_gates[(size_t)(b * TT + t) * 1024 + j];
#pragma unroll 16
    for (int k = 0; k < 256; k++) {
        float w = g_whht[k * 1024 + j];
#pragma unroll
        for (int b = 0; b < BB; b++) acc[b] += w * hs[b * 256 + k];
    }
#pragma unroll
    for (int b = 0; b < BB; b++) g_gacc[b * 1024 + j] = acc[b];
}

// ---------------- final: compute h_9, relu, fc1, relu, fc2 ----------------
__global__ void __launch_bounds__(512) k_fc(const float* __restrict__ fc1w,
                     const float* __restrict__ fc1b,
                     const float* __restrict__ fc2w, const float* __restrict__ fc2b,
                     float* __restrict__ out) {
    __shared__ float last[BB * 256];
    __shared__ float hid[BB * 512];
    __shared__ float red[512];
    int j = threadIdx.x;  // 512 threads
    const float* c8 = g_cbuf[0];  // written by step t=9 at parity (9+1)&1 = 0
    for (int idx = j; idx < BB * 256; idx += 512) {
        int b = idx >> 8, k = idx & 255;
        const float* ga = g_gacc + b * 1024;
        float iv = ga[k], fv = ga[256 + k], gv = ga[512 + k], ov = ga[768 + k];
        float c = sigf(fv) * c8[idx] + sigf(iv) * tanhfast(gv);
        last[idx] = fmaxf(sigf(ov) * tanhfast(c), 0.f);
    }
    __syncthreads();
    for (int b = 0; b < BB; b++) {
        float acc = fc1b[j];
        for (int k = 0; k < 256; k++) acc += last[b * 256 + k] * fc1w[k * 512 + j];
        hid[b * 512 + j] = fmaxf(acc, 0.f);
    }
    __syncthreads();
    for (int b = 0; b < BB; b++) {
        red[j] = hid[b * 512 + j] * fc2w[j];
        __syncthreads();
        for (int o = 256; o; o >>= 1) {
            if (j < o) red[j] += red[j + o];
            __syncthreads();
        }
        if (j == 0) out[b] = red[0] + fc2b[0];
        __syncthreads();
    }
}

// ---------------- host launcher ----------------
extern "C" void kernel_launch(void* const* d_in, const int* in_sizes, int n_in,
                              void* d_out, int out_size) {
    const float* x    = (const float*)d_in[0];
    const int*   ei   = (const int*)d_in[1];
    const float* ea   = (const float*)d_in[2];
    const float* wl0  = (const float*)d_in[3];
    const float* wr0  = (const float*)d_in[4];
    const float* we0  = (const float*)d_in[5];
    const float* att0 = (const float*)d_in[6];
    const float* b0   = (const float*)d_in[7];
    const float* wl1  = (const float*)d_in[8];
    const float* wr1  = (const float*)d_in[9];
    const float* we1  = (const float*)d_in[10];
    const float* att1 = (const float*)d_in[11];
    const float* b1   = (const float*)d_in[12];
    const float* wl2  = (const float*)d_in[13];
    const float* wr2  = (const float*)d_in[14];
    const float* we2  = (const float*)d_in[15];
    const float* att2 = (const float*)d_in[16];
    const float* b2   = (const float*)d_in[17];
    const float* wih  = (const float*)d_in[18];
    const float* whh  = (const float*)d_in[19];
    const float* bih  = (const float*)d_in[20];
    const float* bhh  = (const float*)d_in[21];
    const float* fc1w = (const float*)d_in[22];
    const float* fc1b = (const float*)d_in[23];
    const float* fc2w = (const float*)d_in[24];
    const float* fc2b = (const float*)d_in[25];

    void *p_xl, *p_xr, *p_hA, *p_hB;
    cudaGetSymbolAddress(&p_xl, g_xl);
    cudaGetSymbolAddress(&p_xr, g_xr);
    cudaGetSymbolAddress(&p_hA, g_hA);
    cudaGetSymbolAddress(&p_hB, g_hB);
    float* xl = (float*)p_xl;
    float* xr = (float*)p_xr;
    float* hA = (float*)p_hA;
    float* hB = (float*)p_hB;

    const int M = GNUM * NN;  // 80000
    int aggr_blocks = (GNUM * NN + 7) / 8;  // 8 warps per block

    k_prep_all<<<1, 1024>>>(ei, ea);
    k_whht<<<1024, 256>>>(whh);

    // ---- layer 0: 8 -> 128 ----
    k_gemm_n128<<<dim3(1, M / 128, 2), 256>>>(x, wl0, wr0, xl, xr, 8);
    k_aggr_fused<32><<<aggr_blocks, 256>>>(att0, we0, b0, hA);

    // ---- layer 1: 128 -> 128 ----
    k_gemm_n128<<<dim3(1, M / 128, 2), 256>>>(hA, wl1, wr1, xl, xr, 128);
    k_aggr_fused<32><<<aggr_blocks, 256>>>(att1, we1, b1, hB);

    // ---- layer 2: 128 -> 32 ----
    k_gemm_n32<<<dim3(1, M / 128, 2), 256>>>(hB, wl2, wr2, xl, xr);
    k_aggr_fused<8><<<aggr_blocks, 256>>>(att2, we2, b2, hA);  // hA = emb [40][64000]

    // ---- LSTM input projection (split-K, no atomics) ----
    cudaFuncSetAttribute(k_gates2, cudaFuncAttributeMaxDynamicSharedMemorySize,
                         GNUM * KC * sizeof(float));
    k_gates2<<<dim3(NCHUNK, 16), 256, GNUM * KC * sizeof(float)>>>(hA, wih);
    k_gates_reduce<<<(1024 * GNUM + 255) / 256, 256>>>(bih, bhh);

    // ---- LSTM scan (fused update+gemm) + head ----
    for (int t = 0; t < TT; t++) k_lstm_step<<<8, 128>>>(t);
    k_fc<<<1, 512>>>(fc1w, fc1b, fc2w, fc2b, (float*)d_out);
}

// round 5
// speedup vs baseline: 2.0683x; 1.1540x over previous
#include <cuda_runtime.h>
#include <cstdint>

#define GNUM 40     // B*T graphs
#define NN   2000
#define E0   16000
#define ET   18000
#define TT   10
#define BB   4
#define KC   512
#define NCHUNK 125  // 64000 / KC

// ---------------- scratch ----------------
__device__ float  g_xl[GNUM * NN * 128];
__device__ float  g_xr[GNUM * NN * 128];
__device__ float  g_hA[GNUM * NN * 128];
__device__ float  g_hB[GNUM * NN * 128];
__device__ int    g_rowstart[NN + 1];
__device__ int    g_psrc[ET];
__device__ float2 g_pea[ET];
__device__ float  g_gates[GNUM * 1024];
__device__ float  g_part[NCHUNK * 1024 * GNUM];
__device__ float  g_gacc[BB * 1024];
__device__ float  g_whht[256 * 1024];
__device__ float  g_cbuf[2][BB * 256];

// ---------------- tf32 helpers ----------------
__device__ __forceinline__ uint32_t f2tf(float v) {
    uint32_t r; asm("cvt.rna.tf32.f32 %0, %1;" : "=r"(r) : "f"(v)); return r;
}
__device__ __forceinline__ void split2(float v, float& hi, float& lo) {
    hi = __uint_as_float(f2tf(v));
    lo = __uint_as_float(f2tf(v - hi));
}
__device__ __forceinline__ void mma8(float (&c)[4], const uint32_t (&a)[4],
                                     uint32_t b0, uint32_t b1) {
    asm volatile(
        "mma.sync.aligned.m16n8k8.row.col.f32.tf32.tf32.f32 "
        "{%0,%1,%2,%3},{%4,%5,%6,%7},{%8,%9},{%0,%1,%2,%3};"
        : "+f"(c[0]), "+f"(c[1]), "+f"(c[2]), "+f"(c[3])
        : "r"(a[0]), "r"(a[1]), "r"(a[2]), "r"(a[3]), "r"(b0), "r"(b1));
}

// ---------------- fused prep (1 block) ----------------
__global__ void __launch_bounds__(1024) k_prep_all(const int* __restrict__ ei,
                                                   const float* __restrict__ ea) {
    __shared__ int   sdeg[NN];
    __shared__ int   sscan[1024];
    __shared__ float r0[1024], r1[1024];
    __shared__ float2 smean;
    int t = threadIdx.x;
    float a = 0.f, b = 0.f;
    for (int e = t; e < E0; e += 1024) { a += ea[2 * e]; b += ea[2 * e + 1]; }
    r0[t] = a; r1[t] = b;
    for (int i = t; i < NN; i += 1024) sdeg[i] = 0;
    __syncthreads();
    for (int o = 512; o; o >>= 1) {
        if (t < o) { r0[t] += r0[t + o]; r1[t] += r1[t + o]; }
        __syncthreads();
    }
    if (t == 0) { smean.x = r0[0] / E0; smean.y = r1[0] / E0; }
    for (int e = t; e < ET; e += 1024) {
        int d = (e < E0) ? ei[E0 + e] : (e - E0);
        atomicAdd(&sdeg[d], 1);
    }
    __syncthreads();
    int i0 = 2 * t, i1 = 2 * t + 1;
    int v0 = (i0 < NN) ? sdeg[i0] : 0;
    int v1 = (i1 < NN) ? sdeg[i1] : 0;
    int tot = v0 + v1;
    sscan[t] = tot;
    __syncthreads();
    for (int off = 1; off < 1024; off <<= 1) {
        int x = (t >= off) ? sscan[t - off] : 0;
        __syncthreads();
        sscan[t] += x;
        __syncthreads();
    }
    int base = sscan[t] - tot;
    __syncthreads();
    if (i0 < NN) { g_rowstart[i0] = base;      sdeg[i0] = base; }
    if (i1 < NN) { g_rowstart[i1] = base + v0; sdeg[i1] = base + v0; }
    if (t == 1023) g_rowstart[NN] = sscan[1023];
    __syncthreads();
    float2 mn = smean;
    for (int e = t; e < ET; e += 1024) {
        int s, d;
        if (e < E0) { s = ei[e]; d = ei[E0 + e]; }
        else        { s = d = e - E0; }
        int pos = atomicAdd(&sdeg[d], 1);
        g_psrc[pos] = s;
        float2 v;
        if (e < E0) { v.x = ea[2 * e]; v.y = ea[2 * e + 1]; }
        else        v = mn;
        g_pea[pos] = v;
    }
}

// ---------------- whh transpose + zero c ----------------
__global__ void k_whht(const float* __restrict__ whh) {
    int i = blockIdx.x * 256 + threadIdx.x;
    int j = i >> 8, k = i & 255;
    g_whht[k * 1024 + j] = whh[i];
    if (i < 2 * BB * 256) ((float*)g_cbuf)[i] = 0.f;
}

// ---------------- fp32 GEMM N=128 (layer 0, K=8) ----------------
__global__ void __launch_bounds__(256) k_gemm_n128(const float* __restrict__ A,
                            const float* __restrict__ B0, const float* __restrict__ B1,
                            float* __restrict__ C0, float* __restrict__ C1, int K) {
    const float* B = blockIdx.z ? B1 : B0;
    float*       C = blockIdx.z ? C1 : C0;
    __shared__ float As[8][128];
    __shared__ float Bs[8][128];
    int tid = threadIdx.x;
    int m0 = blockIdx.y * 128;
    int arow = tid >> 1, acol4 = (tid & 1) * 4;
    int brow = tid >> 5, bcol = (tid & 31) * 4;
    int tx = tid & 15, ty = tid >> 4;
    const float* Ap = A + (size_t)(m0 + arow) * K + acol4;
    float4 av = *(const float4*)Ap;
    float4 bv = *(const float4*)(B + (size_t)brow * 128 + bcol);
    float acc[8][8] = {};
    for (int k0 = 0; k0 < K; k0 += 8) {
        As[acol4 + 0][arow] = av.x; As[acol4 + 1][arow] = av.y;
        As[acol4 + 2][arow] = av.z; As[acol4 + 3][arow] = av.w;
        *(float4*)&Bs[brow][bcol] = bv;
        __syncthreads();
        if (k0 + 8 < K) {
            av = *(const float4*)(Ap + k0 + 8);
            bv = *(const float4*)(B + (size_t)(k0 + 8 + brow) * 128 + bcol);
        }
#pragma unroll
        for (int kk = 0; kk < 8; kk++) {
            float a[8], b[8];
            *(float4*)a       = *(const float4*)&As[kk][ty * 8];
            *(float4*)(a + 4) = *(const float4*)&As[kk][ty * 8 + 4];
            *(float4*)b       = *(const float4*)&Bs[kk][tx * 8];
            *(float4*)(b + 4) = *(const float4*)&Bs[kk][tx * 8 + 4];
#pragma unroll
            for (int i = 0; i < 8; i++)
#pragma unroll
                for (int j = 0; j < 8; j++) acc[i][j] += a[i] * b[j];
        }
        __syncthreads();
    }
#pragma unroll
    for (int i = 0; i < 8; i++) {
        float* cp = C + (size_t)(m0 + ty * 8 + i) * 128 + tx * 8;
        *(float4*)cp       = *(float4*)&acc[i][0];
        *(float4*)(cp + 4) = *(float4*)&acc[i][4];
    }
}

// ---------------- tf32 split-mma GEMM: C[M,128] = A[M,128] @ B[128,128] ----------------
// block 256 thr, tile 128x128, k-chunks of 32; hi/lo pre-split in smem; 3-mma split.
__global__ void __launch_bounds__(256) k_gemm_tc128(const float* __restrict__ A,
                            const float* __restrict__ B0, const float* __restrict__ B1,
                            float* __restrict__ C0, float* __restrict__ C1) {
    extern __shared__ float sm[];
    float* As_hi = sm;                 // 128*32
    float* As_lo = sm + 4096;
    float* Bs_hi = sm + 8192;          // 32*136
    float* Bs_lo = sm + 8192 + 4352;
    const float* B = blockIdx.z ? B1 : B0;
    float*       C = blockIdx.z ? C1 : C0;
    int tid = threadIdx.x, lane = tid & 31, warp = tid >> 5;
    int m0 = blockIdx.y * 128;
    int m0w = (warp & 3) * 32, n0w = (warp >> 2) * 64;
    float acc[2][8][4] = {};
    for (int k0 = 0; k0 < 128; k0 += 32) {
        if (k0) __syncthreads();
        // stage A (swizzled: col = k ^ (4*(m&7)))
        for (int idx = tid; idx < 1024; idx += 256) {
            int m = idx >> 3, kq = (idx & 7) * 4;
            float4 v = *(const float4*)(A + (size_t)(m0 + m) * 128 + k0 + kq);
            int c = kq ^ ((m & 7) << 2);
            float4 hi, lo;
            split2(v.x, hi.x, lo.x); split2(v.y, hi.y, lo.y);
            split2(v.z, hi.z, lo.z); split2(v.w, hi.w, lo.w);
            *(float4*)(As_hi + m * 32 + c) = hi;
            *(float4*)(As_lo + m * 32 + c) = lo;
        }
        // stage B (stride 136)
        for (int idx = tid; idx < 1024; idx += 256) {
            int k = idx >> 5, nq = (idx & 31) * 4;
            float4 v = *(const float4*)(B + (size_t)(k0 + k) * 128 + nq);
            float4 hi, lo;
            split2(v.x, hi.x, lo.x); split2(v.y, hi.y, lo.y);
            split2(v.z, hi.z, lo.z); split2(v.w, hi.w, lo.w);
            *(float4*)(Bs_hi + k * 136 + nq) = hi;
            *(float4*)(Bs_lo + k * 136 + nq) = lo;
        }
        __syncthreads();
#pragma unroll
        for (int kk = 0; kk < 32; kk += 8) {
            uint32_t ah[2][4], al[2][4];
#pragma unroll
            for (int mt = 0; mt < 2; mt++) {
                int m = m0w + mt * 16 + (lane >> 2);
                int cb = (m & 7) << 2;
                int k_ = kk + (lane & 3);
                ah[mt][0] = __float_as_uint(As_hi[m * 32 + (k_ ^ cb)]);
                ah[mt][1] = __float_as_uint(As_hi[(m + 8) * 32 + (k_ ^ cb)]);
                ah[mt][2] = __float_as_uint(As_hi[m * 32 + ((k_ + 4) ^ cb)]);
                ah[mt][3] = __float_as_uint(As_hi[(m + 8) * 32 + ((k_ + 4) ^ cb)]);
                al[mt][0] = __float_as_uint(As_lo[m * 32 + (k_ ^ cb)]);
                al[mt][1] = __float_as_uint(As_lo[(m + 8) * 32 + (k_ ^ cb)]);
                al[mt][2] = __float_as_uint(As_lo[m * 32 + ((k_ + 4) ^ cb)]);
                al[mt][3] = __float_as_uint(As_lo[(m + 8) * 32 + ((k_ + 4) ^ cb)]);
            }
#pragma unroll
            for (int nt = 0; nt < 8; nt++) {
                int n = n0w + nt * 8 + (lane >> 2);
                int kr = kk + (lane & 3);
                uint32_t bh0 = __float_as_uint(Bs_hi[kr * 136 + n]);
                uint32_t bh1 = __float_as_uint(Bs_hi[(kr + 4) * 136 + n]);
                uint32_t bl0 = __float_as_uint(Bs_lo[kr * 136 + n]);
                uint32_t bl1 = __float_as_uint(Bs_lo[(kr + 4) * 136 + n]);
#pragma unroll
                for (int mt = 0; mt < 2; mt++) {
                    mma8(acc[mt][nt], ah[mt], bh0, bh1);
                    mma8(acc[mt][nt], ah[mt], bl0, bl1);
                    mma8(acc[mt][nt], al[mt], bh0, bh1);
                }
            }
        }
    }
#pragma unroll
    for (int mt = 0; mt < 2; mt++) {
        int row = m0 + m0w + mt * 16 + (lane >> 2);
#pragma unroll
        for (int nt = 0; nt < 8; nt++) {
            int col = n0w + nt * 8 + 2 * (lane & 3);
            *(float2*)(C + (size_t)row * 128 + col) =
                make_float2(acc[mt][nt][0], acc[mt][nt][1]);
            *(float2*)(C + (size_t)(row + 8) * 128 + col) =
                make_float2(acc[mt][nt][2], acc[mt][nt][3]);
        }
    }
}

// ---------------- fp32 GEMM N=32 (layer 2) ----------------
__global__ void __launch_bounds__(256) k_gemm_n32(const float* __restrict__ A,
                           const float* __restrict__ B0, const float* __restrict__ B1,
                           float* __restrict__ C0, float* __restrict__ C1) {
    const float* B = blockIdx.z ? B1 : B0;
    float*       C = blockIdx.z ? C1 : C0;
    __shared__ float As[16][128];
    __shared__ float Bs[16][32];
    int tid = threadIdx.x;
    int m0 = blockIdx.y * 128;
    int tx = tid & 15, ty = tid >> 4;
    float acc[8][2] = {};
    for (int k0 = 0; k0 < 128; k0 += 16) {
#pragma unroll
        for (int it = 0; it < 2; it++) {
            int idx = tid + it * 256;
            int ar = idx >> 2, ac4 = (idx & 3) * 4;
            float4 av = *(const float4*)(A + (size_t)(m0 + ar) * 128 + k0 + ac4);
            As[ac4 + 0][ar] = av.x; As[ac4 + 1][ar] = av.y;
            As[ac4 + 2][ar] = av.z; As[ac4 + 3][ar] = av.w;
        }
        if (tid < 128) {
            int br = tid >> 3, bc = (tid & 7) * 4;
            *(float4*)&Bs[br][bc] = *(const float4*)(B + (size_t)(k0 + br) * 32 + bc);
        }
        __syncthreads();
#pragma unroll
        for (int kk = 0; kk < 16; kk++) {
            float a[8];
            *(float4*)a       = *(const float4*)&As[kk][ty * 8];
            *(float4*)(a + 4) = *(const float4*)&As[kk][ty * 8 + 4];
            float b0v = Bs[kk][tx * 2], b1v = Bs[kk][tx * 2 + 1];
#pragma unroll
            for (int i = 0; i < 8; i++) { acc[i][0] += a[i] * b0v; acc[i][1] += a[i] * b1v; }
        }
        __syncthreads();
    }
#pragma unroll
    for (int i = 0; i < 8; i++) {
        float2 v; v.x = acc[i][0]; v.y = acc[i][1];
        *(float2*)(C + (size_t)(m0 + ty * 8 + i) * 32 + tx * 2) = v;
    }
}

// ---------------- fused logits + softmax + aggregation ----------------
template <int C>
__global__ void k_aggr_fused(const float* __restrict__ att, const float* __restrict__ We,
                             const float* __restrict__ bias, float* __restrict__ out) {
    int gid  = blockIdx.x * (blockDim.x >> 5) + (threadIdx.x >> 5);
    int lane = threadIdx.x & 31;
    if (gid >= GNUM * NN) return;
    int g = gid / NN, d = gid - g * NN;
    int rs = g_rowstart[d], re = g_rowstart[d + 1];
    if (C == 32) {
        const float* xlg = g_xl + (size_t)g * NN * 128;
        const float* xrr = g_xr + ((size_t)g * NN + d) * 128;
        float xrv[4], attv[4], we0v[4], we1v[4], acc[4] = {};
        float den = 0.f;
        bool hi16 = (lane & 16) != 0, hi8 = (lane & 8) != 0;
#pragma unroll
        for (int h = 0; h < 4; h++) {
            int j = h * 32 + lane;
            xrv[h] = xrr[j]; attv[h] = att[j];
            we0v[h] = We[j]; we1v[h] = We[128 + j];
        }
        // software pipeline: prefetch next edge while computing current
        int s_c = 0; float2 a_c = make_float2(0.f, 0.f); float xlv[4] = {};
        if (rs < re) {
            s_c = g_psrc[rs]; a_c = g_pea[rs];
            const float* xls = xlg + (size_t)s_c * 128;
#pragma unroll
            for (int h = 0; h < 4; h++) xlv[h] = xls[h * 32 + lane];
        }
        for (int i = rs; i < re; i++) {
            int inx = (i + 1 < re) ? i + 1 : i;
            int s_n = g_psrc[inx];
            float2 a_n = g_pea[inx];
            const float* xlsn = xlg + (size_t)s_n * 128;
            float xln[4];
#pragma unroll
            for (int h = 0; h < 4; h++) xln[h] = xlsn[h * 32 + lane];
            float vv[4];
#pragma unroll
            for (int h = 0; h < 4; h++) {
                float v = xlv[h] + xrv[h] + a_c.x * we0v[h] + a_c.y * we1v[h];
                v = v > 0.f ? v : 0.2f * v;
                vv[h] = v * attv[h];
            }
            float m01 = hi16 ? vv[1] : vv[0];
            float o01 = hi16 ? vv[0] : vv[1];
            m01 += __shfl_xor_sync(0xffffffffu, o01, 16);
            float m23 = hi16 ? vv[3] : vv[2];
            float o23 = hi16 ? vv[2] : vv[3];
            m23 += __shfl_xor_sync(0xffffffffu, o23, 16);
            float q  = hi8 ? m23 : m01;
            float rr = hi8 ? m01 : m23;
            q += __shfl_xor_sync(0xffffffffu, rr, 8);
            q += __shfl_xor_sync(0xffffffffu, q, 4);
            q += __shfl_xor_sync(0xffffffffu, q, 2);
            q += __shfl_xor_sync(0xffffffffu, q, 1);
            float p = __expf(q);
            den += p;
            float p0 = __shfl_sync(0xffffffffu, p, 0);
            float p1 = __shfl_sync(0xffffffffu, p, 16);
            float p2 = __shfl_sync(0xffffffffu, p, 8);
            float p3 = __shfl_sync(0xffffffffu, p, 24);
            acc[0] += p0 * xlv[0];
            acc[1] += p1 * xlv[1];
            acc[2] += p2 * xlv[2];
            acc[3] += p3 * xlv[3];
            s_c = s_n; a_c = a_n;
#pragma unroll
            for (int h = 0; h < 4; h++) xlv[h] = xln[h];
        }
        float dh[4];
        dh[0] = __shfl_sync(0xffffffffu, den, 0);
        dh[1] = __shfl_sync(0xffffffffu, den, 16);
        dh[2] = __shfl_sync(0xffffffffu, den, 8);
        dh[3] = __shfl_sync(0xffffffffu, den, 24);
        float* op = out + ((size_t)g * NN + d) * 128;
#pragma unroll
        for (int h = 0; h < 4; h++)
            op[h * 32 + lane] = fmaxf(acc[h] / (dh[h] + 1e-16f) + bias[h * 32 + lane], 0.f);
    } else {  // C == 8
        const float* xlg = g_xl + (size_t)g * NN * 32;
        float xrv = g_xr[((size_t)g * NN + d) * 32 + lane];
        float attv = att[lane];
        float we0v = We[lane], we1v = We[32 + lane];
        float acc = 0.f, den = 0.f;
#pragma unroll 2
        for (int i = rs; i < re; i++) {
            int s = g_psrc[i];
            float2 a = g_pea[i];
            float xlv = xlg[(size_t)s * 32 + lane];
            float v = xlv + xrv + a.x * we0v + a.y * we1v;
            v = v > 0.f ? v : 0.2f * v;
            v *= attv;
            v += __shfl_xor_sync(0xffffffffu, v, 4);
            v += __shfl_xor_sync(0xffffffffu, v, 2);
            v += __shfl_xor_sync(0xffffffffu, v, 1);
            float p = __expf(v);
            den += p; acc += p * xlv;
        }
        out[((size_t)g * NN + d) * 32 + lane] =
            fmaxf(acc / (den + 1e-16f) + bias[lane], 0.f);
    }
}

// ---------------- LSTM input projection via tf32 split-mma ----------------
// partials[chunk][j][g] = sum_{k in chunk} wih[j][k] * emb[g][k];  j on M, g on N (5 tiles).
// grid (125 chunks, 2 j-halves); block 256 = 8 warps x 64 j; warp: 4 mtiles x 5 ntiles.
__global__ void __launch_bounds__(256)
k_gates_tc(const float* __restrict__ emb, const float* __restrict__ wih) {
    extern __shared__ float sm[];
    float* eh = sm;              // [40][260] hi
    float* el = sm + 40 * 260;   // [40][260] lo
    int tid = threadIdx.x, lane = tid & 31, warp = tid >> 5;
    int chunk = blockIdx.x;
    int j0w = blockIdx.y * 512 + warp * 64;
    float acc[4][5][4] = {};
#pragma unroll 1
    for (int sub = 0; sub < 2; sub++) {
        int kbase = chunk * KC + sub * 256;
        if (sub) __syncthreads();
        for (int idx = tid; idx < 40 * 64; idx += 256) {
            int gg = idx >> 6, kq = (idx & 63) * 4;
            float4 v = *(const float4*)(emb + (size_t)gg * 64000 + kbase + kq);
            float4 hi, lo;
            split2(v.x, hi.x, lo.x); split2(v.y, hi.y, lo.y);
            split2(v.z, hi.z, lo.z); split2(v.w, hi.w, lo.w);
            *(float4*)(eh + gg * 260 + kq) = hi;
            *(float4*)(el + gg * 260 + kq) = lo;
        }
        __syncthreads();
#pragma unroll 1
        for (int kk = 0; kk < 256; kk += 8) {
            uint32_t ah[4][4], al[4][4];
#pragma unroll
            for (int mt = 0; mt < 4; mt++) {
                const float* ap = wih + (size_t)(j0w + mt * 16 + (lane >> 2)) * 64000
                                + kbase + kk + (lane & 3);
                float v0 = __ldg(ap);
                float v1 = __ldg(ap + (size_t)8 * 64000);
                float v2 = __ldg(ap + 4);
                float v3 = __ldg(ap + (size_t)8 * 64000 + 4);
                float h, l;
                split2(v0, h, l); ah[mt][0] = __float_as_uint(h); al[mt][0] = __float_as_uint(l);
                split2(v1, h, l); ah[mt][1] = __float_as_uint(h); al[mt][1] = __float_as_uint(l);
                split2(v2, h, l); ah[mt][2] = __float_as_uint(h); al[mt][2] = __float_as_uint(l);
                split2(v3, h, l); ah[mt][3] = __float_as_uint(h); al[mt][3] = __float_as_uint(l);
            }
#pragma unroll
            for (int nt = 0; nt < 5; nt++) {
                int gg = nt * 8 + (lane >> 2);
                int kr = kk + (lane & 3);
                uint32_t bh0 = __float_as_uint(eh[gg * 260 + kr]);
                uint32_t bh1 = __float_as_uint(eh[gg * 260 + kr + 4]);
                uint32_t bl0 = __float_as_uint(el[gg * 260 + kr]);
                uint32_t bl1 = __float_as_uint(el[gg * 260 + kr + 4]);
#pragma unroll
                for (int mt = 0; mt < 4; mt++) {
                    mma8(acc[mt][nt], ah[mt], bh0, bh1);
                    mma8(acc[mt][nt], ah[mt], bl0, bl1);
                    mma8(acc[mt][nt], al[mt], bh0, bh1);
                }
            }
        }
    }
    float* pbase = g_part + (size_t)chunk * 1024 * GNUM;
#pragma unroll
    for (int mt = 0; mt < 4; mt++) {
        int j = j0w + mt * 16 + (lane >> 2);
#pragma unroll
        for (int nt = 0; nt < 5; nt++) {
            int gg = nt * 8 + 2 * (lane & 3);
            *(float2*)(pbase + (size_t)j * GNUM + gg) =
                make_float2(acc[mt][nt][0], acc[mt][nt][1]);
            *(float2*)(pbase + (size_t)(j + 8) * GNUM + gg) =
                make_float2(acc[mt][nt][2], acc[mt][nt][3]);
        }
    }
}

// ---------------- reduce partials + biases -> g_gates ----------------
__global__ void k_gates_reduce(const float* __restrict__ bih, const float* __restrict__ bhh) {
    int i = blockIdx.x * blockDim.x + threadIdx.x;  // i = j*40 + gi
    if (i >= 1024 * GNUM) return;
    int j = i / GNUM, gi = i - j * GNUM;
    float s = bih[j] + bhh[j];
    for (int c = 0; c < NCHUNK; c++) s += g_part[(size_t)c * 1024 * GNUM + i];
    g_gates[gi * 1024 + j] = s;
}

// ---------------- LSTM ----------------
__device__ __forceinline__ float sigf(float x) { return 1.f / (1.f + __expf(-x)); }
__device__ __forceinline__ float tanhfast(float x) { return 1.f - 2.f / (__expf(2.f * x) + 1.f); }

__global__ void __launch_bounds__(128) k_lstm_step(int t) {  // grid 8 x 128
    __shared__ float hs[BB * 256];
    int tid = threadIdx.x;
    int j = blockIdx.x * 128 + tid;
    if (t == 0) {
        for (int i = tid; i < BB * 256; i += 128) hs[i] = 0.f;
    } else {
        const float* cprev = g_cbuf[t & 1];
        float* cnew = g_cbuf[(t + 1) & 1];
        for (int idx = tid; idx < BB * 256; idx += 128) {
            int b = idx >> 8, k = idx & 255;
            const float* ga = g_gacc + b * 1024;
            float iv = ga[k], fv = ga[256 + k], gv = ga[512 + k], ov = ga[768 + k];
            float c = sigf(fv) * cprev[idx] + sigf(iv) * tanhfast(gv);
            if (blockIdx.x == 0) cnew[idx] = c;
            hs[idx] = sigf(ov) * tanhfast(c);
        }
    }
    __syncthreads();
    float acc[BB];
#pragma unroll
    for (int b = 0; b < BB; b++) acc[b] = g_gates[(size_t)(b * TT + t) * 1024 + j];
#pragma unroll 16
    for (int k = 0; k < 256; k++) {
        float w = g_whht[k * 1024 + j];
#pragma unroll
        for (int b = 0; b < BB; b++) acc[b] += w * hs[b * 256 + k];
    }
#pragma unroll
    for (int b = 0; b < BB; b++) g_gacc[b * 1024 + j] = acc[b];
}

// ---------------- final head ----------------
__global__ void __launch_bounds__(512) k_fc(const float* __restrict__ fc1w,
                     const float* __restrict__ fc1b,
                     const float* __restrict__ fc2w, const float* __restrict__ fc2b,
                     float* __restrict__ out) {
    __shared__ float last[BB * 256];
    __shared__ float hid[BB * 512];
    __shared__ float red[512];
    int j = threadIdx.x;
    const float* c8 = g_cbuf[0];
    for (int idx = j; idx < BB * 256; idx += 512) {
        int b = idx >> 8, k = idx & 255;
        const float* ga = g_gacc + b * 1024;
        float iv = ga[k], fv = ga[256 + k], gv = ga[512 + k], ov = ga[768 + k];
        float c = sigf(fv) * c8[idx] + sigf(iv) * tanhfast(gv);
        last[idx] = fmaxf(sigf(ov) * tanhfast(c), 0.f);
    }
    __syncthreads();
    for (int b = 0; b < BB; b++) {
        float acc = fc1b[j];
        for (int k = 0; k < 256; k++) acc += last[b * 256 + k] * fc1w[k * 512 + j];
        hid[b * 512 + j] = fmaxf(acc, 0.f);
    }
    __syncthreads();
    for (int b = 0; b < BB; b++) {
        red[j] = hid[b * 512 + j] * fc2w[j];
        __syncthreads();
        for (int o = 256; o; o >>= 1) {
            if (j < o) red[j] += red[j + o];
            __syncthreads();
        }
        if (j == 0) out[b] = red[0] + fc2b[0];
        __syncthreads();
    }
}

// ---------------- host launcher ----------------
extern "C" void kernel_launch(void* const* d_in, const int* in_sizes, int n_in,
                              void* d_out, int out_size) {
    const float* x    = (const float*)d_in[0];
    const int*   ei   = (const int*)d_in[1];
    const float* ea   = (const float*)d_in[2];
    const float* wl0  = (const float*)d_in[3];
    const float* wr0  = (const float*)d_in[4];
    const float* we0  = (const float*)d_in[5];
    const float* att0 = (const float*)d_in[6];
    const float* b0   = (const float*)d_in[7];
    const float* wl1  = (const float*)d_in[8];
    const float* wr1  = (const float*)d_in[9];
    const float* we1  = (const float*)d_in[10];
    const float* att1 = (const float*)d_in[11];
    const float* b1   = (const float*)d_in[12];
    const float* wl2  = (const float*)d_in[13];
    const float* wr2  = (const float*)d_in[14];
    const float* we2  = (const float*)d_in[15];
    const float* att2 = (const float*)d_in[16];
    const float* b2   = (const float*)d_in[17];
    const float* wih  = (const float*)d_in[18];
    const float* whh  = (const float*)d_in[19];
    const float* bih  = (const float*)d_in[20];
    const float* bhh  = (const float*)d_in[21];
    const float* fc1w = (const float*)d_in[22];
    const float* fc1b = (const float*)d_in[23];
    const float* fc2w = (const float*)d_in[24];
    const float* fc2b = (const float*)d_in[25];

    void *p_xl, *p_xr, *p_hA, *p_hB;
    cudaGetSymbolAddress(&p_xl, g_xl);
    cudaGetSymbolAddress(&p_xr, g_xr);
    cudaGetSymbolAddress(&p_hA, g_hA);
    cudaGetSymbolAddress(&p_hB, g_hB);
    float* xl = (float*)p_xl;
    float* xr = (float*)p_xr;
    float* hA = (float*)p_hA;
    float* hB = (float*)p_hB;

    const int M = GNUM * NN;  // 80000
    int aggr_blocks = (GNUM * NN + 7) / 8;

    const int SMEM_TC   = (8192 + 8704) * 4;       // 67584
    const int SMEM_GATE = 2 * 40 * 260 * 4;        // 83200
    cudaFuncSetAttribute(k_gemm_tc128, cudaFuncAttributeMaxDynamicSharedMemorySize, SMEM_TC);
    cudaFuncSetAttribute(k_gates_tc, cudaFuncAttributeMaxDynamicSharedMemorySize, SMEM_GATE);

    k_prep_all<<<1, 1024>>>(ei, ea);
    k_whht<<<1024, 256>>>(whh);

    // ---- layer 0: 8 -> 128 ----
    k_gemm_n128<<<dim3(1, M / 128, 2), 256>>>(x, wl0, wr0, xl, xr, 8);
    k_aggr_fused<32><<<aggr_blocks, 256>>>(att0, we0, b0, hA);

    // ---- layer 1: 128 -> 128 (tf32 split-mma) ----
    k_gemm_tc128<<<dim3(1, M / 128, 2), 256, SMEM_TC>>>(hA, wl1, wr1, xl, xr);
    k_aggr_fused<32><<<aggr_blocks, 256>>>(att1, we1, b1, hB);

    // ---- layer 2: 128 -> 32 ----
    k_gemm_n32<<<dim3(1, M / 128, 2), 256>>>(hB, wl2, wr2, xl, xr);
    k_aggr_fused<8><<<aggr_blocks, 256>>>(att2, we2, b2, hA);  // hA = emb [40][64000]

    // ---- LSTM input projection (tf32 split-mma, split-K) ----
    k_gates_tc<<<dim3(NCHUNK, 2), 256, SMEM_GATE>>>(hA, wih);
    k_gates_reduce<<<(1024 * GNUM + 255) / 256, 256>>>(bih, bhh);

    // ---- LSTM scan + head ----
    for (int t = 0; t < TT; t++) k_lstm_step<<<8, 128>>>(t);
    k_fc<<<1, 512>>>(fc1w, fc1b, fc2w, fc2b, (float*)d_out);
}

// round 8
// speedup vs baseline: 2.1205x; 1.0252x over previous
#include <cuda_runtime.h>
#include <cstdint>

#define GNUM 40
#define NN   2000
#define E0   16000
#define ET   18000
#define TT   10
#define BB   4
#define KC   512
#define NCHUNK 125

// ---------------- scratch ----------------
__device__ float  g_xl[GNUM * NN * 128];
__device__ float  g_xr[GNUM * NN * 128];
__device__ float  g_hA[GNUM * NN * 128];
__device__ float  g_hB[GNUM * NN * 128];
__device__ int    g_rowstart[NN + 1];
__device__ int    g_psrc[ET];
__device__ float2 g_pea[ET];
__device__ float  g_gates[GNUM * 1024];
__device__ float  g_part[NCHUNK * 1024 * GNUM];
__device__ float  g_gacc[BB * 1024];
__device__ float  g_whht[256 * 1024];
__device__ float  g_cbuf[2][BB * 256];

// ---------------- tf32 helpers ----------------
__device__ __forceinline__ uint32_t f2tf(float v) {
    uint32_t r; asm("cvt.rna.tf32.f32 %0, %1;" : "=r"(r) : "f"(v)); return r;
}
__device__ __forceinline__ void split2(float v, float& hi, float& lo) {
    hi = __uint_as_float(f2tf(v));
    lo = __uint_as_float(f2tf(v - hi));
}
__device__ __forceinline__ void mma8(float (&c)[4], const uint32_t (&a)[4],
                                     uint32_t b0, uint32_t b1) {
    asm volatile(
        "mma.sync.aligned.m16n8k8.row.col.f32.tf32.tf32.f32 "
        "{%0,%1,%2,%3},{%4,%5,%6,%7},{%8,%9},{%0,%1,%2,%3};"
        : "+f"(c[0]), "+f"(c[1]), "+f"(c[2]), "+f"(c[3])
        : "r"(a[0]), "r"(a[1]), "r"(a[2]), "r"(a[3]), "r"(b0), "r"(b1));
}

// ---------------- fused prep (1 block) ----------------
__global__ void __launch_bounds__(1024) k_prep_all(const int* __restrict__ ei,
                                                   const float* __restrict__ ea) {
    __shared__ int   sdeg[NN];
    __shared__ int   sscan[1024];
    __shared__ float r0[1024], r1[1024];
    __shared__ float2 smean;
    int t = threadIdx.x;
    float a = 0.f, b = 0.f;
    for (int e = t; e < E0; e += 1024) { a += ea[2 * e]; b += ea[2 * e + 1]; }
    r0[t] = a; r1[t] = b;
    for (int i = t; i < NN; i += 1024) sdeg[i] = 0;
    __syncthreads();
    for (int o = 512; o; o >>= 1) {
        if (t < o) { r0[t] += r0[t + o]; r1[t] += r1[t + o]; }
        __syncthreads();
    }
    if (t == 0) { smean.x = r0[0] / E0; smean.y = r1[0] / E0; }
    for (int e = t; e < ET; e += 1024) {
        int d = (e < E0) ? ei[E0 + e] : (e - E0);
        atomicAdd(&sdeg[d], 1);
    }
    __syncthreads();
    int i0 = 2 * t, i1 = 2 * t + 1;
    int v0 = (i0 < NN) ? sdeg[i0] : 0;
    int v1 = (i1 < NN) ? sdeg[i1] : 0;
    int tot = v0 + v1;
    sscan[t] = tot;
    __syncthreads();
    for (int off = 1; off < 1024; off <<= 1) {
        int x = (t >= off) ? sscan[t - off] : 0;
        __syncthreads();
        sscan[t] += x;
        __syncthreads();
    }
    int base = sscan[t] - tot;
    __syncthreads();
    if (i0 < NN) { g_rowstart[i0] = base;      sdeg[i0] = base; }
    if (i1 < NN) { g_rowstart[i1] = base + v0; sdeg[i1] = base + v0; }
    if (t == 1023) g_rowstart[NN] = sscan[1023];
    __syncthreads();
    float2 mn = smean;
    for (int e = t; e < ET; e += 1024) {
        int s, d;
        if (e < E0) { s = ei[e]; d = ei[E0 + e]; }
        else        { s = d = e - E0; }
        int pos = atomicAdd(&sdeg[d], 1);
        g_psrc[pos] = s;
        float2 v;
        if (e < E0) { v.x = ea[2 * e]; v.y = ea[2 * e + 1]; }
        else        v = mn;
        g_pea[pos] = v;
    }
}

// ---------------- whh transpose + zero c buffers ----------------
__global__ void k_whht(const float* __restrict__ whh) {
    int i = blockIdx.x * 256 + threadIdx.x;
    int j = i >> 8, k = i & 255;
    g_whht[k * 1024 + j] = whh[i];
    if (i < 2 * BB * 256) ((float*)g_cbuf)[i] = 0.f;
}

// ---------------- fp32 GEMM N=128 (layer 0, K=8) ----------------
__global__ void __launch_bounds__(256) k_gemm_n128(const float* __restrict__ A,
                            const float* __restrict__ B0, const float* __restrict__ B1,
                            float* __restrict__ C0, float* __restrict__ C1, int K) {
    const float* B = blockIdx.z ? B1 : B0;
    float*       C = blockIdx.z ? C1 : C0;
    __shared__ float As[8][128];
    __shared__ float Bs[8][128];
    int tid = threadIdx.x;
    int m0 = blockIdx.y * 128;
    int arow = tid >> 1, acol4 = (tid & 1) * 4;
    int brow = tid >> 5, bcol = (tid & 31) * 4;
    int tx = tid & 15, ty = tid >> 4;
    const float* Ap = A + (size_t)(m0 + arow) * K + acol4;
    float4 av = *(const float4*)Ap;
    float4 bv = *(const float4*)(B + (size_t)brow * 128 + bcol);
    float acc[8][8] = {};
    for (int k0 = 0; k0 < K; k0 += 8) {
        As[acol4 + 0][arow] = av.x; As[acol4 + 1][arow] = av.y;
        As[acol4 + 2][arow] = av.z; As[acol4 + 3][arow] = av.w;
        *(float4*)&Bs[brow][bcol] = bv;
        __syncthreads();
        if (k0 + 8 < K) {
            av = *(const float4*)(Ap + k0 + 8);
            bv = *(const float4*)(B + (size_t)(k0 + 8 + brow) * 128 + bcol);
        }
#pragma unroll
        for (int kk = 0; kk < 8; kk++) {
            float a[8], b[8];
            *(float4*)a       = *(const float4*)&As[kk][ty * 8];
            *(float4*)(a + 4) = *(const float4*)&As[kk][ty * 8 + 4];
            *(float4*)b       = *(const float4*)&Bs[kk][tx * 8];
            *(float4*)(b + 4) = *(const float4*)&Bs[kk][tx * 8 + 4];
#pragma unroll
            for (int i = 0; i < 8; i++)
#pragma unroll
                for (int j = 0; j < 8; j++) acc[i][j] += a[i] * b[j];
        }
        __syncthreads();
    }
#pragma unroll
    for (int i = 0; i < 8; i++) {
        float* cp = C + (size_t)(m0 + ty * 8 + i) * 128 + tx * 8;
        *(float4*)cp       = *(float4*)&acc[i][0];
        *(float4*)(cp + 4) = *(float4*)&acc[i][4];
    }
}

// ---------------- tf32 split-mma GEMM N=128 ----------------
__global__ void __launch_bounds__(256) k_gemm_tc128(const float* __restrict__ A,
                            const float* __restrict__ B0, const float* __restrict__ B1,
                            float* __restrict__ C0, float* __restrict__ C1) {
    extern __shared__ float sm[];
    float* As_hi = sm;
    float* As_lo = sm + 4096;
    float* Bs_hi = sm + 8192;
    float* Bs_lo = sm + 8192 + 4352;
    const float* B = blockIdx.z ? B1 : B0;
    float*       C = blockIdx.z ? C1 : C0;
    int tid = threadIdx.x, lane = tid & 31, warp = tid >> 5;
    int m0 = blockIdx.y * 128;
    int m0w = (warp & 3) * 32, n0w = (warp >> 2) * 64;
    float acc[2][8][4] = {};
    for (int k0 = 0; k0 < 128; k0 += 32) {
        if (k0) __syncthreads();
        for (int idx = tid; idx < 1024; idx += 256) {
            int m = idx >> 3, kq = (idx & 7) * 4;
            float4 v = *(const float4*)(A + (size_t)(m0 + m) * 128 + k0 + kq);
            int c = kq ^ ((m & 7) << 2);
            float4 hi, lo;
            split2(v.x, hi.x, lo.x); split2(v.y, hi.y, lo.y);
            split2(v.z, hi.z, lo.z); split2(v.w, hi.w, lo.w);
            *(float4*)(As_hi + m * 32 + c) = hi;
            *(float4*)(As_lo + m * 32 + c) = lo;
        }
        for (int idx = tid; idx < 1024; idx += 256) {
            int k = idx >> 5, nq = (idx & 31) * 4;
            float4 v = *(const float4*)(B + (size_t)(k0 + k) * 128 + nq);
            float4 hi, lo;
            split2(v.x, hi.x, lo.x); split2(v.y, hi.y, lo.y);
            split2(v.z, hi.z, lo.z); split2(v.w, hi.w, lo.w);
            *(float4*)(Bs_hi + k * 136 + nq) = hi;
            *(float4*)(Bs_lo + k * 136 + nq) = lo;
        }
        __syncthreads();
#pragma unroll
        for (int kk = 0; kk < 32; kk += 8) {
            uint32_t ah[2][4], al[2][4];
#pragma unroll
            for (int mt = 0; mt < 2; mt++) {
                int m = m0w + mt * 16 + (lane >> 2);
                int cb = (m & 7) << 2;
                int k_ = kk + (lane & 3);
                ah[mt][0] = __float_as_uint(As_hi[m * 32 + (k_ ^ cb)]);
                ah[mt][1] = __float_as_uint(As_hi[(m + 8) * 32 + (k_ ^ cb)]);
                ah[mt][2] = __float_as_uint(As_hi[m * 32 + ((k_ + 4) ^ cb)]);
                ah[mt][3] = __float_as_uint(As_hi[(m + 8) * 32 + ((k_ + 4) ^ cb)]);
                al[mt][0] = __float_as_uint(As_lo[m * 32 + (k_ ^ cb)]);
                al[mt][1] = __float_as_uint(As_lo[(m + 8) * 32 + (k_ ^ cb)]);
                al[mt][2] = __float_as_uint(As_lo[m * 32 + ((k_ + 4) ^ cb)]);
                al[mt][3] = __float_as_uint(As_lo[(m + 8) * 32 + ((k_ + 4) ^ cb)]);
            }
#pragma unroll
            for (int nt = 0; nt < 8; nt++) {
                int n = n0w + nt * 8 + (lane >> 2);
                int kr = kk + (lane & 3);
                uint32_t bh0 = __float_as_uint(Bs_hi[kr * 136 + n]);
                uint32_t bh1 = __float_as_uint(Bs_hi[(kr + 4) * 136 + n]);
                uint32_t bl0 = __float_as_uint(Bs_lo[kr * 136 + n]);
                uint32_t bl1 = __float_as_uint(Bs_lo[(kr + 4) * 136 + n]);
#pragma unroll
                for (int mt = 0; mt < 2; mt++) {
                    mma8(acc[mt][nt], ah[mt], bh0, bh1);
                    mma8(acc[mt][nt], ah[mt], bl0, bl1);
                    mma8(acc[mt][nt], al[mt], bh0, bh1);
                }
            }
        }
    }
#pragma unroll
    for (int mt = 0; mt < 2; mt++) {
        int row = m0 + m0w + mt * 16 + (lane >> 2);
#pragma unroll
        for (int nt = 0; nt < 8; nt++) {
            int col = n0w + nt * 8 + 2 * (lane & 3);
            *(float2*)(C + (size_t)row * 128 + col) =
                make_float2(acc[mt][nt][0], acc[mt][nt][1]);
            *(float2*)(C + (size_t)(row + 8) * 128 + col) =
                make_float2(acc[mt][nt][2], acc[mt][nt][3]);
        }
    }
}

// ---------------- tf32 split-mma GEMM N=32 (both weights, one pass over A) -------------
// B staged ONCE as full [128,32]; fragment reads use GLOBAL row (k0 + kr).  <-- R7 fix
__global__ void __launch_bounds__(256) k_gemm_tc32(const float* __restrict__ A,
                            const float* __restrict__ B0, const float* __restrict__ B1,
                            float* __restrict__ C0, float* __restrict__ C1) {
    extern __shared__ float sm[];
    float* As_hi = sm;                 // 4096
    float* As_lo = sm + 4096;          // 4096
    float* Bh0 = sm + 8192;            // 4608 each (128 x 36)
    float* Bl0 = sm + 12800;
    float* Bh1 = sm + 17408;
    float* Bl1 = sm + 22016;
    int tid = threadIdx.x, lane = tid & 31, warp = tid >> 5;
    int m0 = blockIdx.x * 128;
    for (int idx = tid; idx < 4096; idx += 256) {
        int k = idx >> 5, n = idx & 31;
        float h, l;
        split2(B0[idx], h, l); Bh0[k * 36 + n] = h; Bl0[k * 36 + n] = l;
        split2(B1[idx], h, l); Bh1[k * 36 + n] = h; Bl1[k * 36 + n] = l;
    }
    float acc[2][4][4] = {};
    for (int k0 = 0; k0 < 128; k0 += 32) {
        __syncthreads();
        for (int idx = tid; idx < 1024; idx += 256) {
            int m = idx >> 3, kq = (idx & 7) * 4;
            float4 v = *(const float4*)(A + (size_t)(m0 + m) * 128 + k0 + kq);
            int c = kq ^ ((m & 7) << 2);
            float4 hi, lo;
            split2(v.x, hi.x, lo.x); split2(v.y, hi.y, lo.y);
            split2(v.z, hi.z, lo.z); split2(v.w, hi.w, lo.w);
            *(float4*)(As_hi + m * 32 + c) = hi;
            *(float4*)(As_lo + m * 32 + c) = lo;
        }
        __syncthreads();
#pragma unroll
        for (int kk = 0; kk < 32; kk += 8) {
            uint32_t ah[4], al[4];
            int m = warp * 16 + (lane >> 2);
            int cb = (m & 7) << 2;
            int k_ = kk + (lane & 3);
            ah[0] = __float_as_uint(As_hi[m * 32 + (k_ ^ cb)]);
            ah[1] = __float_as_uint(As_hi[(m + 8) * 32 + (k_ ^ cb)]);
            ah[2] = __float_as_uint(As_hi[m * 32 + ((k_ + 4) ^ cb)]);
            ah[3] = __float_as_uint(As_hi[(m + 8) * 32 + ((k_ + 4) ^ cb)]);
            al[0] = __float_as_uint(As_lo[m * 32 + (k_ ^ cb)]);
            al[1] = __float_as_uint(As_lo[(m + 8) * 32 + (k_ ^ cb)]);
            al[2] = __float_as_uint(As_lo[m * 32 + ((k_ + 4) ^ cb)]);
            al[3] = __float_as_uint(As_lo[(m + 8) * 32 + ((k_ + 4) ^ cb)]);
            int kg = k0 + kk + (lane & 3);   // GLOBAL B row (the fix)
#pragma unroll
            for (int nt = 0; nt < 4; nt++) {
                int n = nt * 8 + (lane >> 2);
                uint32_t bh0 = __float_as_uint(Bh0[kg * 36 + n]);
                uint32_t bh1 = __float_as_uint(Bh0[(kg + 4) * 36 + n]);
                uint32_t bl0 = __float_as_uint(Bl0[kg * 36 + n]);
                uint32_t bl1 = __float_as_uint(Bl0[(kg + 4) * 36 + n]);
                mma8(acc[0][nt], ah, bh0, bh1);
                mma8(acc[0][nt], ah, bl0, bl1);
                mma8(acc[0][nt], al, bh0, bh1);
                uint32_t ch0 = __float_as_uint(Bh1[kg * 36 + n]);
                uint32_t ch1 = __float_as_uint(Bh1[(kg + 4) * 36 + n]);
                uint32_t cl0 = __float_as_uint(Bl1[kg * 36 + n]);
                uint32_t cl1 = __float_as_uint(Bl1[(kg + 4) * 36 + n]);
                mma8(acc[1][nt], ah, ch0, ch1);
                mma8(acc[1][nt], ah, cl0, cl1);
                mma8(acc[1][nt], al, ch0, ch1);
            }
        }
    }
#pragma unroll
    for (int z = 0; z < 2; z++) {
        float* C = z ? C1 : C0;
        int row = m0 + warp * 16 + (lane >> 2);
#pragma unroll
        for (int nt = 0; nt < 4; nt++) {
            int col = nt * 8 + 2 * (lane & 3);
            *(float2*)(C + (size_t)row * 32 + col) =
                make_float2(acc[z][nt][0], acc[z][nt][1]);
            *(float2*)(C + (size_t)(row + 8) * 32 + col) =
                make_float2(acc[z][nt][2], acc[z][nt][3]);
        }
    }
}

// ---------------- aggr layers 0/1: canonical layout, 4 graphs per warp ----------------
__global__ void __launch_bounds__(256) k_aggr32c(const float* __restrict__ att,
        const float* __restrict__ We, const float* __restrict__ bias,
        const float* __restrict__ xl, const float* __restrict__ xr,
        float* __restrict__ out) {
    int gid  = blockIdx.x * 8 + (threadIdx.x >> 5);
    int lane = threadIdx.x & 31;
    if (gid >= NN * (GNUM / 4)) return;
    int d  = gid / (GNUM / 4);
    int g0 = (gid - d * (GNUM / 4)) * 4;
    int rs = g_rowstart[d], re = g_rowstart[d + 1];
    float attv[4], we0v[4], we1v[4];
    float xrv[4][4], acc[4][4] = {}, den[4] = {};
#pragma unroll
    for (int h = 0; h < 4; h++) {
        int j = h * 32 + lane;
        attv[h] = att[j]; we0v[h] = We[j]; we1v[h] = We[128 + j];
    }
#pragma unroll
    for (int q = 0; q < 4; q++) {
        const float* xrr = xr + ((size_t)(g0 + q) * NN + d) * 128;
#pragma unroll
        for (int h = 0; h < 4; h++) xrv[q][h] = xrr[h * 32 + lane];
    }
    bool hi16 = (lane & 16) != 0, hi8 = (lane & 8) != 0;
    for (int i = rs; i < re; i++) {
        int s = g_psrc[i];
        float2 a = g_pea[i];
        float ew[4];
#pragma unroll
        for (int h = 0; h < 4; h++) ew[h] = a.x * we0v[h] + a.y * we1v[h];
        float xlv[4][4];
#pragma unroll
        for (int q = 0; q < 4; q++) {
            const float* xls = xl + ((size_t)(g0 + q) * NN + s) * 128;
#pragma unroll
            for (int h = 0; h < 4; h++) xlv[q][h] = xls[h * 32 + lane];
        }
#pragma unroll
        for (int q = 0; q < 4; q++) {
            float vv[4];
#pragma unroll
            for (int h = 0; h < 4; h++) {
                float v = xlv[q][h] + xrv[q][h] + ew[h];
                v = v > 0.f ? v : 0.2f * v;
                vv[h] = v * attv[h];
            }
            float m01 = hi16 ? vv[1] : vv[0];
            float o01 = hi16 ? vv[0] : vv[1];
            m01 += __shfl_xor_sync(0xffffffffu, o01, 16);
            float m23 = hi16 ? vv[3] : vv[2];
            float o23 = hi16 ? vv[2] : vv[3];
            m23 += __shfl_xor_sync(0xffffffffu, o23, 16);
            float qq = hi8 ? m23 : m01;
            float rr = hi8 ? m01 : m23;
            qq += __shfl_xor_sync(0xffffffffu, rr, 8);
            qq += __shfl_xor_sync(0xffffffffu, qq, 4);
            qq += __shfl_xor_sync(0xffffffffu, qq, 2);
            qq += __shfl_xor_sync(0xffffffffu, qq, 1);
            float p = __expf(qq);
            den[q] += p;
            float p0 = __shfl_sync(0xffffffffu, p, 0);
            float p1 = __shfl_sync(0xffffffffu, p, 16);
            float p2 = __shfl_sync(0xffffffffu, p, 8);
            float p3 = __shfl_sync(0xffffffffu, p, 24);
            acc[q][0] += p0 * xlv[q][0];
            acc[q][1] += p1 * xlv[q][1];
            acc[q][2] += p2 * xlv[q][2];
            acc[q][3] += p3 * xlv[q][3];
        }
    }
#pragma unroll
    for (int q = 0; q < 4; q++) {
        float dh[4];
        dh[0] = __shfl_sync(0xffffffffu, den[q], 0);
        dh[1] = __shfl_sync(0xffffffffu, den[q], 16);
        dh[2] = __shfl_sync(0xffffffffu, den[q], 8);
        dh[3] = __shfl_sync(0xffffffffu, den[q], 24);
        float* op = out + ((size_t)(g0 + q) * NN + d) * 128;
#pragma unroll
        for (int h = 0; h < 4; h++)
            op[h * 32 + lane] = fmaxf(acc[q][h] / (dh[h] + 1e-16f) + bias[h * 32 + lane], 0.f);
    }
}

// ---------------- aggr layer 2: canonical layout, 4 graphs per warp ----------------
__global__ void __launch_bounds__(256) k_aggr8c(const float* __restrict__ att,
        const float* __restrict__ We, const float* __restrict__ bias,
        const float* __restrict__ xl, const float* __restrict__ xr,
        float* __restrict__ out) {
    int gid  = blockIdx.x * 8 + (threadIdx.x >> 5);
    int lane = threadIdx.x & 31;
    if (gid >= NN * (GNUM / 4)) return;
    int d  = gid / (GNUM / 4);
    int g0 = (gid - d * (GNUM / 4)) * 4;
    int rs = g_rowstart[d], re = g_rowstart[d + 1];
    float attv = att[lane], we0v = We[lane], we1v = We[32 + lane];
    float xrv[4], acc[4] = {}, den[4] = {};
#pragma unroll
    for (int q = 0; q < 4; q++)
        xrv[q] = xr[((size_t)(g0 + q) * NN + d) * 32 + lane];
    for (int i = rs; i < re; i++) {
        int s = g_psrc[i];
        float2 a = g_pea[i];
        float ew = a.x * we0v + a.y * we1v;
        float xlv[4];
#pragma unroll
        for (int q = 0; q < 4; q++)
            xlv[q] = xl[((size_t)(g0 + q) * NN + s) * 32 + lane];
#pragma unroll
        for (int q = 0; q < 4; q++) {
            float v = xlv[q] + xrv[q] + ew;
            v = (v > 0.f ? v : 0.2f * v) * attv;
            v += __shfl_xor_sync(0xffffffffu, v, 4);
            v += __shfl_xor_sync(0xffffffffu, v, 2);
            v += __shfl_xor_sync(0xffffffffu, v, 1);
            float p = __expf(v);
            den[q] += p;
            acc[q] += p * xlv[q];
        }
    }
    float bv = bias[lane];
#pragma unroll
    for (int q = 0; q < 4; q++)
        out[((size_t)(g0 + q) * NN + d) * 32 + lane] =
            fmaxf(acc[q] / (den[q] + 1e-16f) + bv, 0.f);
}

// ---------------- LSTM input projection (tf32, split-K) ----------------
__global__ void __launch_bounds__(256)
k_gates_tc(const float* __restrict__ emb, const float* __restrict__ wih) {
    extern __shared__ float sm[];
    float* eh = sm;
    float* el = sm + 40 * 260;
    int tid = threadIdx.x, lane = tid & 31, warp = tid >> 5;
    int chunk = blockIdx.x;
    int j0w = blockIdx.y * 512 + warp * 64;
    float acc[4][5][4] = {};
#pragma unroll 1
    for (int sub = 0; sub < 2; sub++) {
        int kbase = chunk * KC + sub * 256;
        if (sub) __syncthreads();
        for (int idx = tid; idx < 40 * 64; idx += 256) {
            int gg = idx >> 6, kq = (idx & 63) * 4;
            float4 v = *(const float4*)(emb + (size_t)gg * 64000 + kbase + kq);
            float4 hi, lo;
            split2(v.x, hi.x, lo.x); split2(v.y, hi.y, lo.y);
            split2(v.z, hi.z, lo.z); split2(v.w, hi.w, lo.w);
            *(float4*)(eh + gg * 260 + kq) = hi;
            *(float4*)(el + gg * 260 + kq) = lo;
        }
        __syncthreads();
#pragma unroll 1
        for (int kk = 0; kk < 256; kk += 8) {
            uint32_t ah[4][4], al[4][4];
#pragma unroll
            for (int mt = 0; mt < 4; mt++) {
                const float* ap = wih + (size_t)(j0w + mt * 16 + (lane >> 2)) * 64000
                                + kbase + kk + (lane & 3);
                float v0 = __ldg(ap);
                float v1 = __ldg(ap + (size_t)8 * 64000);
                float v2 = __ldg(ap + 4);
                float v3 = __ldg(ap + (size_t)8 * 64000 + 4);
                float h, l;
                split2(v0, h, l); ah[mt][0] = __float_as_uint(h); al[mt][0] = __float_as_uint(l);
                split2(v1, h, l); ah[mt][1] = __float_as_uint(h); al[mt][1] = __float_as_uint(l);
                split2(v2, h, l); ah[mt][2] = __float_as_uint(h); al[mt][2] = __float_as_uint(l);
                split2(v3, h, l); ah[mt][3] = __float_as_uint(h); al[mt][3] = __float_as_uint(l);
            }
#pragma unroll
            for (int nt = 0; nt < 5; nt++) {
                int gg = nt * 8 + (lane >> 2);
                int kr = kk + (lane & 3);
                uint32_t bh0 = __float_as_uint(eh[gg * 260 + kr]);
                uint32_t bh1 = __float_as_uint(eh[gg * 260 + kr + 4]);
                uint32_t bl0 = __float_as_uint(el[gg * 260 + kr]);
                uint32_t bl1 = __float_as_uint(el[gg * 260 + kr + 4]);
#pragma unroll
                for (int mt = 0; mt < 4; mt++) {
                    mma8(acc[mt][nt], ah[mt], bh0, bh1);
                    mma8(acc[mt][nt], ah[mt], bl0, bl1);
                    mma8(acc[mt][nt], al[mt], bh0, bh1);
                }
            }
        }
    }
    float* pbase = g_part + (size_t)chunk * 1024 * GNUM;
#pragma unroll
    for (int mt = 0; mt < 4; mt++) {
        int j = j0w + mt * 16 + (lane >> 2);
#pragma unroll
        for (int nt = 0; nt < 5; nt++) {
            int gg = nt * 8 + 2 * (lane & 3);
            *(float2*)(pbase + (size_t)j * GNUM + gg) =
                make_float2(acc[mt][nt][0], acc[mt][nt][1]);
            *(float2*)(pbase + (size_t)(j + 8) * GNUM + gg) =
                make_float2(acc[mt][nt][2], acc[mt][nt][3]);
        }
    }
}

__global__ void k_gates_reduce(const float* __restrict__ bih, const float* __restrict__ bhh) {
    int i = blockIdx.x * blockDim.x + threadIdx.x;
    if (i >= 1024 * GNUM) return;
    int j = i / GNUM, gi = i - j * GNUM;
    float s = bih[j] + bhh[j];
    for (int c = 0; c < NCHUNK; c++) s += g_part[(size_t)c * 1024 * GNUM + i];
    g_gates[gi * 1024 + j] = s;
}

// ---------------- LSTM (per-step, fused update) ----------------
__device__ __forceinline__ float sigf(float x) { return 1.f / (1.f + __expf(-x)); }
__device__ __forceinline__ float tanhfast(float x) { return 1.f - 2.f / (__expf(2.f * x) + 1.f); }

__global__ void __launch_bounds__(128) k_lstm_step(int t) {  // grid 8 x 128
    __shared__ float hs[BB * 256];
    int tid = threadIdx.x;
    int j = blockIdx.x * 128 + tid;
    if (t == 0) {
        for (int i = tid; i < BB * 256; i += 128) hs[i] = 0.f;
    } else {
        const float* cprev = g_cbuf[t & 1];
        float* cnew = g_cbuf[(t + 1) & 1];
        for (int idx = tid; idx < BB * 256; idx += 128) {
            int b = idx >> 8, k = idx & 255;
            const float* ga = g_gacc + b * 1024;
            float iv = ga[k], fv = ga[256 + k], gv = ga[512 + k], ov = ga[768 + k];
            float c = sigf(fv) * cprev[idx] + sigf(iv) * tanhfast(gv);
            if (blockIdx.x == 0) cnew[idx] = c;
            hs[idx] = sigf(ov) * tanhfast(c);
        }
    }
    __syncthreads();
    float acc[BB];
#pragma unroll
    for (int b = 0; b < BB; b++) acc[b] = g_gates[(size_t)(b * TT + t) * 1024 + j];
#pragma unroll 16
    for (int k = 0; k < 256; k++) {
        float w = g_whht[k * 1024 + j];
#pragma unroll
        for (int b = 0; b < BB; b++) acc[b] += w * hs[b * 256 + k];
    }
#pragma unroll
    for (int b = 0; b < BB; b++) g_gacc[b * 1024 + j] = acc[b];
}

// ---------------- final head ----------------
__global__ void __launch_bounds__(512) k_fc(const float* __restrict__ fc1w,
                     const float* __restrict__ fc1b,
                     const float* __restrict__ fc2w, const float* __restrict__ fc2b,
                     float* __restrict__ out) {
    __shared__ float last[BB * 256];
    __shared__ float hid[BB * 512];
    __shared__ float red[512];
    int j = threadIdx.x;
    const float* c8 = g_cbuf[0];  // written by step t=9 at parity (9+1)&1 = 0
    for (int idx = j; idx < BB * 256; idx += 512) {
        int b = idx >> 8, k = idx & 255;
        const float* ga = g_gacc + b * 1024;
        float iv = ga[k], fv = ga[256 + k], gv = ga[512 + k], ov = ga[768 + k];
        float c = sigf(fv) * c8[idx] + sigf(iv) * tanhfast(gv);
        last[idx] = fmaxf(sigf(ov) * tanhfast(c), 0.f);
    }
    __syncthreads();
    for (int b = 0; b < BB; b++) {
        float acc = fc1b[j];
        for (int k = 0; k < 256; k++) acc += last[b * 256 + k] * fc1w[k * 512 + j];
        hid[b * 512 + j] = fmaxf(acc, 0.f);
    }
    __syncthreads();
    for (int b = 0; b < BB; b++) {
        red[j] = hid[b * 512 + j] * fc2w[j];
        __syncthreads();
        for (int o = 256; o; o >>= 1) {
            if (j < o) red[j] += red[j + o];
            __syncthreads();
        }
        if (j == 0) out[b] = red[0] + fc2b[0];
        __syncthreads();
    }
}

// ---------------- host launcher ----------------
extern "C" void kernel_launch(void* const* d_in, const int* in_sizes, int n_in,
                              void* d_out, int out_size) {
    const float* x    = (const float*)d_in[0];
    const int*   ei   = (const int*)d_in[1];
    const float* ea   = (const float*)d_in[2];
    const float* wl0  = (const float*)d_in[3];
    const float* wr0  = (const float*)d_in[4];
    const float* we0  = (const float*)d_in[5];
    const float* att0 = (const float*)d_in[6];
    const float* b0   = (const float*)d_in[7];
    const float* wl1  = (const float*)d_in[8];
    const float* wr1  = (const float*)d_in[9];
    const float* we1  = (const float*)d_in[10];
    const float* att1 = (const float*)d_in[11];
    const float* b1   = (const float*)d_in[12];
    const float* wl2  = (const float*)d_in[13];
    const float* wr2  = (const float*)d_in[14];
    const float* we2  = (const float*)d_in[15];
    const float* att2 = (const float*)d_in[16];
    const float* b2   = (const float*)d_in[17];
    const float* wih  = (const float*)d_in[18];
    const float* whh  = (const float*)d_in[19];
    const float* bih  = (const float*)d_in[20];
    const float* bhh  = (const float*)d_in[21];
    const float* fc1w = (const float*)d_in[22];
    const float* fc1b = (const float*)d_in[23];
    const float* fc2w = (const float*)d_in[24];
    const float* fc2b = (const float*)d_in[25];

    void *p_xl, *p_xr, *p_hA, *p_hB;
    cudaGetSymbolAddress(&p_xl, g_xl);
    cudaGetSymbolAddress(&p_xr, g_xr);
    cudaGetSymbolAddress(&p_hA, g_hA);
    cudaGetSymbolAddress(&p_hB, g_hB);
    float* xl = (float*)p_xl;
    float* xr = (float*)p_xr;
    float* hA = (float*)p_hA;
    float* hB = (float*)p_hB;

    const int M = GNUM * NN;
    const int SMEM_TC   = (8192 + 8704) * 4;
    const int SMEM_TC32 = 26624 * 4;
    const int SMEM_GATE = 2 * 40 * 260 * 4;
    cudaFuncSetAttribute(k_gemm_tc128, cudaFuncAttributeMaxDynamicSharedMemorySize, SMEM_TC);
    cudaFuncSetAttribute(k_gemm_tc32, cudaFuncAttributeMaxDynamicSharedMemorySize, SMEM_TC32);
    cudaFuncSetAttribute(k_gates_tc, cudaFuncAttributeMaxDynamicSharedMemorySize, SMEM_GATE);

    k_prep_all<<<1, 1024>>>(ei, ea);
    k_whht<<<1024, 256>>>(whh);

    // ---- layer 0: 8 -> 128 ----
    k_gemm_n128<<<dim3(1, M / 128, 2), 256>>>(x, wl0, wr0, xl, xr, 8);
    k_aggr32c<<<2500, 256>>>(att0, we0, b0, xl, xr, hA);

    // ---- layer 1: 128 -> 128 (tf32) ----
    k_gemm_tc128<<<dim3(1, M / 128, 2), 256, SMEM_TC>>>(hA, wl1, wr1, xl, xr);
    k_aggr32c<<<2500, 256>>>(att1, we1, b1, xl, xr, hB);

    // ---- layer 2: 128 -> 32 (tf32, both weights in one pass) ----
    k_gemm_tc32<<<M / 128, 256, SMEM_TC32>>>(hB, wl2, wr2, xl, xr);
    k_aggr8c<<<2500, 256>>>(att2, we2, b2, xl, xr, hA);  // hA = emb [40][64000]

    // ---- LSTM input projection ----
    k_gates_tc<<<dim3(NCHUNK, 2), 256, SMEM_GATE>>>(hA, wih);
    k_gates_reduce<<<(1024 * GNUM + 255) / 256, 256>>>(bih, bhh);

    // ---- LSTM scan + head ----
    for (int t = 0; t < TT; t++) k_lstm_step<<<8, 128>>>(t);
    k_fc<<<1, 512>>>(fc1w, fc1b, fc2w, fc2b, (float*)d_out);
}